// round 1
// baseline (speedup 1.0000x reference)
#include <cuda_runtime.h>
#include <math.h>

#define B_  4
#define T_  24
#define N_  2048
#define D_  256
#define H_  8
#define HD_ 32
#define MTOK (B_*T_*N_)          // 196608 tokens
#define ELEMS ((size_t)MTOK * D_) // 50,331,648

// Scratch (device globals; allocation-free per harness rules)
__device__ float g_q [ELEMS];
__device__ float g_k [ELEMS];
__device__ float g_v [ELEMS];
__device__ float g_os[ELEMS];
__device__ float g_ot[ELEMS];

// ---------------------------------------------------------------------------
// GEMM1: qkv[M,768] = x[M,256] * w_qkv[768,256]^T   (both K-contiguous / "TN")
// Tile 128x128x16, 256 threads, 8x8 microtile. Epilogue scatters to q/k/v.
// ---------------------------------------------------------------------------
__global__ __launch_bounds__(256, 2)
void gemm_qkv_kernel(const float* __restrict__ A, const float* __restrict__ Bw,
                     float* __restrict__ outq, float* __restrict__ outk,
                     float* __restrict__ outv)
{
    const int K = 256;
    __shared__ float As[16][132];
    __shared__ float Bs[16][132];
    const int tid = threadIdx.x;
    const int m0 = blockIdx.y * 128;
    const int n0 = blockIdx.x * 128;

    const int ty = tid >> 4;       // 0..15
    const int tx = tid & 15;       // 0..15
    const int lr = tid >> 2;       // 0..63  (load row within 64-row group)
    const int lk = (tid & 3) * 4;  // 0,4,8,12

    float acc[8][8];
    #pragma unroll
    for (int i = 0; i < 8; i++)
        #pragma unroll
        for (int j = 0; j < 8; j++) acc[i][j] = 0.f;

    for (int k0 = 0; k0 < K; k0 += 16) {
        #pragma unroll
        for (int i = 0; i < 2; i++) {
            int row = lr + i * 64;
            float4 a = *(const float4*)(A + (size_t)(m0 + row) * K + k0 + lk);
            As[lk+0][row] = a.x; As[lk+1][row] = a.y;
            As[lk+2][row] = a.z; As[lk+3][row] = a.w;
            float4 b = *(const float4*)(Bw + (size_t)(n0 + row) * K + k0 + lk);
            Bs[lk+0][row] = b.x; Bs[lk+1][row] = b.y;
            Bs[lk+2][row] = b.z; Bs[lk+3][row] = b.w;
        }
        __syncthreads();
        #pragma unroll
        for (int kk = 0; kk < 16; kk++) {
            float a[8], b[8];
            *(float4*)&a[0] = *(const float4*)&As[kk][ty*4];
            *(float4*)&a[4] = *(const float4*)&As[kk][ty*4 + 64];
            *(float4*)&b[0] = *(const float4*)&Bs[kk][tx*4];
            *(float4*)&b[4] = *(const float4*)&Bs[kk][tx*4 + 64];
            #pragma unroll
            for (int i = 0; i < 8; i++)
                #pragma unroll
                for (int j = 0; j < 8; j++)
                    acc[i][j] = fmaf(a[i], b[j], acc[i][j]);
        }
        __syncthreads();
    }

    // whole 128-wide tile lies inside one of q/k/v (n0 multiple of 128)
    const int sel = n0 >> 8;
    float* dst = (sel == 0) ? outq : ((sel == 1) ? outk : outv);
    const int nl0 = n0 & 255;
    #pragma unroll
    for (int i = 0; i < 8; i++) {
        int m = m0 + ((i < 4) ? (ty*4 + i) : (64 + ty*4 + (i - 4)));
        #pragma unroll
        for (int jj = 0; jj < 2; jj++) {
            int nl = nl0 + tx*4 + jj*64;
            float4 val = make_float4(acc[i][jj*4+0], acc[i][jj*4+1],
                                     acc[i][jj*4+2], acc[i][jj*4+3]);
            *(float4*)(dst + (size_t)m * 256 + nl) = val;
        }
    }
}

// ---------------------------------------------------------------------------
// GEMM2: out[M,256] = out_s[M,256]*W[:, :256]^T + out_t[M,256]*W[:,256:]^T + b
// W row-major (256,512).
// ---------------------------------------------------------------------------
__global__ __launch_bounds__(256, 2)
void gemm_out_kernel(const float* __restrict__ A1, const float* __restrict__ A2,
                     const float* __restrict__ W, const float* __restrict__ bias,
                     float* __restrict__ out)
{
    __shared__ float As[16][132];
    __shared__ float Bs[16][132];
    const int tid = threadIdx.x;
    const int m0 = blockIdx.y * 128;
    const int n0 = blockIdx.x * 128;

    const int ty = tid >> 4;
    const int tx = tid & 15;
    const int lr = tid >> 2;
    const int lk = (tid & 3) * 4;

    float acc[8][8];
    #pragma unroll
    for (int i = 0; i < 8; i++)
        #pragma unroll
        for (int j = 0; j < 8; j++) acc[i][j] = 0.f;

    for (int k0 = 0; k0 < 512; k0 += 16) {
        const float* Ap = (k0 < 256) ? A1 : A2;
        const int ka = k0 & 255;
        #pragma unroll
        for (int i = 0; i < 2; i++) {
            int row = lr + i * 64;
            float4 a = *(const float4*)(Ap + (size_t)(m0 + row) * 256 + ka + lk);
            As[lk+0][row] = a.x; As[lk+1][row] = a.y;
            As[lk+2][row] = a.z; As[lk+3][row] = a.w;
            float4 b = *(const float4*)(W + (size_t)(n0 + row) * 512 + k0 + lk);
            Bs[lk+0][row] = b.x; Bs[lk+1][row] = b.y;
            Bs[lk+2][row] = b.z; Bs[lk+3][row] = b.w;
        }
        __syncthreads();
        #pragma unroll
        for (int kk = 0; kk < 16; kk++) {
            float a[8], b[8];
            *(float4*)&a[0] = *(const float4*)&As[kk][ty*4];
            *(float4*)&a[4] = *(const float4*)&As[kk][ty*4 + 64];
            *(float4*)&b[0] = *(const float4*)&Bs[kk][tx*4];
            *(float4*)&b[4] = *(const float4*)&Bs[kk][tx*4 + 64];
            #pragma unroll
            for (int i = 0; i < 8; i++)
                #pragma unroll
                for (int j = 0; j < 8; j++)
                    acc[i][j] = fmaf(a[i], b[j], acc[i][j]);
        }
        __syncthreads();
    }

    #pragma unroll
    for (int i = 0; i < 8; i++) {
        int m = m0 + ((i < 4) ? (ty*4 + i) : (64 + ty*4 + (i - 4)));
        #pragma unroll
        for (int jj = 0; jj < 2; jj++) {
            int n = n0 + tx*4 + jj*64;
            float4 val = make_float4(acc[i][jj*4+0] + bias[n+0],
                                     acc[i][jj*4+1] + bias[n+1],
                                     acc[i][jj*4+2] + bias[n+2],
                                     acc[i][jj*4+3] + bias[n+3]);
            *(float4*)(out + (size_t)m * 256 + n) = val;
        }
    }
}

// ---------------------------------------------------------------------------
// L2-normalize q and k in place, per 32-element head chunk (one warp/chunk).
// ---------------------------------------------------------------------------
__global__ void l2norm_kernel(float* __restrict__ q, float* __restrict__ k,
                              int nChunks)
{
    int idx = blockIdx.x * blockDim.x + threadIdx.x;
    int chunk = idx >> 5;
    int lane  = idx & 31;
    if (chunk >= nChunks) return;
    size_t base = (size_t)chunk * 32 + lane;

    float vq = q[base];
    float ss = vq * vq;
    #pragma unroll
    for (int o = 16; o; o >>= 1) ss += __shfl_xor_sync(0xffffffffu, ss, o);
    q[base] = vq / fmaxf(sqrtf(ss), 1e-12f);

    float vk = k[base];
    ss = vk * vk;
    #pragma unroll
    for (int o = 16; o; o >>= 1) ss += __shfl_xor_sync(0xffffffffu, ss, o);
    k[base] = vk / fmaxf(sqrtf(ss), 1e-12f);
}

// ---------------------------------------------------------------------------
// Spatial linear attention: attend over N=2048, batch (B*T, H).
// One block (256 thr = 8 warps) per (bt, h). Two passes.
// ---------------------------------------------------------------------------
__global__ __launch_bounds__(256)
void spatial_attn_kernel(const float* __restrict__ q, const float* __restrict__ k,
                         const float* __restrict__ v, float* __restrict__ o)
{
    const int bt = blockIdx.x;   // 0..95
    const int h  = blockIdx.y;   // 0..7
    const int tid = threadIdx.x;
    const int w = tid >> 5, lane = tid & 31;

    __shared__ float kvs[32][33];
    __shared__ float kss[32];
    for (int i = tid; i < 32*33; i += 256) (&kvs[0][0])[i] = 0.f;
    if (tid < 32) kss[tid] = 0.f;
    __syncthreads();

    const size_t baseBT = (size_t)bt * N_ * D_ + h * HD_;

    float acc[32];
    #pragma unroll
    for (int m = 0; m < 32; m++) acc[m] = 0.f;
    float ksd = 0.f;

    for (int l = w; l < N_; l += 8) {
        size_t off = baseBT + (size_t)l * D_ + lane;
        float kd = k[off];
        float vd = v[off];
        ksd += kd;
        #pragma unroll
        for (int m = 0; m < 32; m++)
            acc[m] = fmaf(__shfl_sync(0xffffffffu, kd, m), vd, acc[m]);
    }
    #pragma unroll
    for (int m = 0; m < 32; m++) atomicAdd(&kvs[m][lane], acc[m]);
    atomicAdd(&kss[lane], ksd);
    __syncthreads();

    const float kssd = kss[lane];
    for (int l = w; l < N_; l += 8) {
        size_t off = baseBT + (size_t)l * D_ + lane;
        float qd = q[off];
        float vd = v[off];
        float den = qd * kssd;
        #pragma unroll
        for (int o2 = 16; o2; o2 >>= 1) den += __shfl_xor_sync(0xffffffffu, den, o2);
        den = fmaxf(den + (float)N_, 1e-5f);
        float num = (float)N_ * vd;
        #pragma unroll
        for (int m = 0; m < 32; m++)
            num = fmaf(__shfl_sync(0xffffffffu, qd, m), kvs[m][lane], num);
        o[off] = num / den;
    }
}

// ---------------------------------------------------------------------------
// Temporal linear attention: attend over T=24, batch (B*N, H).
// One block per (b,n); warp = head; kvs fully register-resident.
// Writes directly in (B,T,N,D) layout.
// ---------------------------------------------------------------------------
__global__ __launch_bounds__(256)
void temporal_attn_kernel(const float* __restrict__ q, const float* __restrict__ k,
                          const float* __restrict__ v, float* __restrict__ o)
{
    const int bn = blockIdx.x;       // 0..8191
    const int b = bn >> 11;          // /2048
    const int n = bn & 2047;
    const int tid = threadIdx.x;
    const int h = tid >> 5, lane = tid & 31;

    const size_t base = ((size_t)b * T_ * N_ + n) * D_ + h * HD_ + lane;
    const size_t strideT = (size_t)N_ * D_;

    float acc[32];
    #pragma unroll
    for (int m = 0; m < 32; m++) acc[m] = 0.f;
    float vreg[T_];
    float ksd = 0.f;

    #pragma unroll
    for (int t = 0; t < T_; t++) {
        size_t off = base + (size_t)t * strideT;
        float kd = k[off];
        float vd = v[off];
        vreg[t] = vd;
        ksd += kd;
        #pragma unroll
        for (int m = 0; m < 32; m++)
            acc[m] = fmaf(__shfl_sync(0xffffffffu, kd, m), vd, acc[m]);
    }

    #pragma unroll
    for (int t = 0; t < T_; t++) {
        size_t off = base + (size_t)t * strideT;
        float qd = q[off];
        float den = qd * ksd;
        #pragma unroll
        for (int o2 = 16; o2; o2 >>= 1) den += __shfl_xor_sync(0xffffffffu, den, o2);
        den = fmaxf(den + (float)T_, 1e-5f);
        float num = (float)T_ * vreg[t];
        #pragma unroll
        for (int m = 0; m < 32; m++)
            num = fmaf(__shfl_sync(0xffffffffu, qd, m), acc[m], num);
        o[off] = num / den;
    }
}

// ---------------------------------------------------------------------------
extern "C" void kernel_launch(void* const* d_in, const int* in_sizes, int n_in,
                              void* d_out, int out_size)
{
    const float* x     = (const float*)d_in[0];
    const float* w_qkv = (const float*)d_in[1];
    const float* w_out = (const float*)d_in[2];
    const float* b_out = (const float*)d_in[3];
    float* out = (float*)d_out;

    float *q, *k, *v, *os, *ot;
    cudaGetSymbolAddress((void**)&q,  g_q);
    cudaGetSymbolAddress((void**)&k,  g_k);
    cudaGetSymbolAddress((void**)&v,  g_v);
    cudaGetSymbolAddress((void**)&os, g_os);
    cudaGetSymbolAddress((void**)&ot, g_ot);

    // 1) QKV projection
    {
        dim3 grid(768 / 128, MTOK / 128);
        gemm_qkv_kernel<<<grid, 256>>>(x, w_qkv, q, k, v);
    }
    // 2) l2norm q, k (per head chunk of 32)
    {
        int nChunks = MTOK * H_;                 // 1,572,864
        int threads = 256;
        int blocks = (nChunks * 32 + threads - 1) / threads;
        l2norm_kernel<<<blocks, threads>>>(q, k, nChunks);
    }
    // 3) spatial attention
    {
        dim3 grid(B_ * T_, H_);
        spatial_attn_kernel<<<grid, 256>>>(q, k, v, os);
    }
    // 4) temporal attention
    {
        temporal_attn_kernel<<<B_ * N_, 256>>>(q, k, v, ot);
    }
    // 5) output projection + bias
    {
        dim3 grid(256 / 128, MTOK / 128);
        gemm_out_kernel<<<grid, 256>>>(os, ot, w_out, b_out, out);
    }
}

// round 2
// speedup vs baseline: 1.3721x; 1.3721x over previous
#include <cuda_runtime.h>
#include <math.h>
#include <stdint.h>

#define B_  4
#define T_  24
#define N_  2048
#define D_  256
#define H_  8
#define HD_ 32
#define MTOK (B_*T_*N_)           // 196608 tokens
#define ELEMS ((size_t)MTOK * D_) // 50,331,648

// Scratch (device globals; allocation-free per harness rules)
__device__ float g_q [ELEMS];
__device__ float g_k [ELEMS];
__device__ float g_v [ELEMS];
__device__ float g_os[ELEMS];
__device__ float g_ot[ELEMS];

// ---------------------------------------------------------------------------
// tf32 mma.sync GEMM: C[M,N] = A[M,K]*B[N,K]^T  (both K-contiguous, "TN")
// CTA tile 128x128x32, 256 threads = 8 warps (2 m x 4 n), warp tile 64x32.
// mma.sync.aligned.m16n8k8.row.col.f32.tf32.tf32.f32
// SMEM layout per operand per buffer: 4 k-blocks of 8, each block row-major
// [128 rows][8 words], k within block permuted s = (k&3)*2 | (k>>2&1), then
// XORed with (row&3)<<1 (keeps (c,c+4) pairs adjacent for LDS.64 frag loads,
// makes the strided STS scatter bank-conflict-free). Block stride 1026 words
// (2-word pad) so the 4 k-blocks land on different banks for the writer.
// ---------------------------------------------------------------------------
#define GBK   32
#define KBWRD 1026                 // words per k-block (128*8 + 2 pad)
#define OPWRD (4*KBWRD)            // words per operand per buffer = 4104
#define SMEM_BYTES (2*2*OPWRD*4)   // 65664

__device__ __forceinline__ uint32_t f2tf32(float f) {
    uint32_t u;
    asm("cvt.rna.tf32.f32 %0, %1;" : "=r"(u) : "f"(f));
    return u;
}

#define MMA_TF32(d, a0, a1, a2, a3, b0, b1)                                   \
    asm volatile("mma.sync.aligned.m16n8k8.row.col.f32.tf32.tf32.f32 "        \
                 "{%0,%1,%2,%3}, {%4,%5,%6,%7}, {%8,%9}, {%0,%1,%2,%3};"      \
                 : "+f"(d[0]), "+f"(d[1]), "+f"(d[2]), "+f"(d[3])             \
                 : "r"(a0), "r"(a1), "r"(a2), "r"(a3), "r"(b0), "r"(b1))

template<int KTOT, bool DUAL, bool BIAS>
__global__ __launch_bounds__(256, 1)
void mma_gemm(const float* __restrict__ A0, const float* __restrict__ A1,
              const float* __restrict__ Bw, int ldb,
              const float* __restrict__ bias,
              float* __restrict__ o0, float* __restrict__ o1,
              float* __restrict__ o2)
{
    extern __shared__ uint32_t sh[];
    const int tid  = threadIdx.x;
    const int lane = tid & 31;
    const int wid  = tid >> 5;
    const int wm   = wid & 1;        // 0..1 -> m offset wm*64
    const int wn   = wid >> 1;       // 0..3 -> n offset wn*32
    const int m0   = blockIdx.y * 128;
    const int n0g  = blockIdx.x * 128;

    // loader-side constants
    const int kq    = tid & 7;                 // which float4 along K (0..7)
    const int rbase = tid >> 3;                // base row (0..31)
    const int kb    = kq >> 1;                 // k-block 0..3
    const int par   = kq & 1;                  // low/high half of block
    const int xr    = (rbase & 3) << 1;        // row swizzle (row&3 invariant +32)

    // reader-side constants
    const int r   = lane >> 2;                 // 0..7
    const int cx  = ((lane & 3) << 1) ^ ((r & 3) << 1);

    float acc[4][4][4];
    #pragma unroll
    for (int i = 0; i < 4; i++)
        #pragma unroll
        for (int j = 0; j < 4; j++)
            #pragma unroll
            for (int c = 0; c < 4; c++) acc[i][j][c] = 0.f;

    float4 sA[4], sB[4];

    const int KT = KTOT / GBK;

    // ---- load tile kt into registers ----
    auto load_tiles = [&](int kt) {
        const int k0 = kt * GBK;
        #pragma unroll
        for (int i = 0; i < 4; i++) {
            int row = rbase + 32 * i;
            const float* pa;
            if (DUAL) {
                int kg = k0 + kq * 4;
                pa = (kg < 256) ? (A0 + (size_t)(m0 + row) * 256 + kg)
                                : (A1 + (size_t)(m0 + row) * 256 + (kg - 256));
            } else {
                pa = A0 + (size_t)(m0 + row) * KTOT + k0 + kq * 4;
            }
            sA[i] = *(const float4*)pa;
            sB[i] = *(const float4*)(Bw + (size_t)(n0g + row) * ldb + k0 + kq * 4);
        }
    };

    // ---- convert + store registers into SMEM buffer ----
    auto store_tiles = [&](int buf) {
        uint32_t* sa = sh + buf * 2 * OPWRD;
        uint32_t* sb = sa + OPWRD;
        #pragma unroll
        for (int i = 0; i < 4; i++) {
            int row  = rbase + 32 * i;
            int base = kb * KBWRD + row * 8;
            sa[base + (((0 << 1) | par) ^ xr)] = f2tf32(sA[i].x);
            sa[base + (((1 << 1) | par) ^ xr)] = f2tf32(sA[i].y);
            sa[base + (((2 << 1) | par) ^ xr)] = f2tf32(sA[i].z);
            sa[base + (((3 << 1) | par) ^ xr)] = f2tf32(sA[i].w);
            sb[base + (((0 << 1) | par) ^ xr)] = f2tf32(sB[i].x);
            sb[base + (((1 << 1) | par) ^ xr)] = f2tf32(sB[i].y);
            sb[base + (((2 << 1) | par) ^ xr)] = f2tf32(sB[i].z);
            sb[base + (((3 << 1) | par) ^ xr)] = f2tf32(sB[i].w);
        }
    };

    // ---- mma over one SMEM buffer ----
    auto compute = [&](int buf) {
        const uint32_t* sa = sh + buf * 2 * OPWRD;
        const uint32_t* sb = sa + OPWRD;
        #pragma unroll
        for (int kk = 0; kk < 4; kk++) {
            uint2 bf[4];
            #pragma unroll
            for (int nt = 0; nt < 4; nt++) {
                int n = wn * 32 + nt * 8 + r;
                bf[nt] = *(const uint2*)&sb[kk * KBWRD + n * 8 + cx];
            }
            uint2 alo[4], ahi[4];
            #pragma unroll
            for (int mt = 0; mt < 4; mt++) {
                int row = wm * 64 + mt * 16 + r;
                alo[mt] = *(const uint2*)&sa[kk * KBWRD + row * 8 + cx];
                ahi[mt] = *(const uint2*)&sa[kk * KBWRD + (row + 8) * 8 + cx];
            }
            #pragma unroll
            for (int mt = 0; mt < 4; mt++)
                #pragma unroll
                for (int nt = 0; nt < 4; nt++)
                    MMA_TF32(acc[mt][nt], alo[mt].x, ahi[mt].x,
                             alo[mt].y, ahi[mt].y, bf[nt].x, bf[nt].y);
        }
    };

    // ---- double-buffered main loop ----
    load_tiles(0);
    store_tiles(0);
    __syncthreads();
    for (int kt = 0; kt < KT; kt++) {
        if (kt + 1 < KT) load_tiles(kt + 1);
        compute(kt & 1);
        if (kt + 1 < KT) store_tiles((kt + 1) & 1);
        __syncthreads();
    }

    // ---- epilogue ----
    const int c2 = (lane & 3) << 1;
    #pragma unroll
    for (int mt = 0; mt < 4; mt++) {
        int m = m0 + wm * 64 + mt * 16 + r;
        #pragma unroll
        for (int nt = 0; nt < 4; nt++) {
            int n = n0g + wn * 32 + nt * 8 + c2;
            float* a = acc[mt][nt];
            if (BIAS) {
                float b0 = bias[n], b1 = bias[n + 1];
                *(float2*)(o0 + (size_t)m * 256 + n)       = make_float2(a[0] + b0, a[1] + b1);
                *(float2*)(o0 + (size_t)(m + 8) * 256 + n) = make_float2(a[2] + b0, a[3] + b1);
            } else {
                int sel = n >> 8;
                float* dst = (sel == 0) ? o0 : ((sel == 1) ? o1 : o2);
                int col = n & 255;
                *(float2*)(dst + (size_t)m * 256 + col)       = make_float2(a[0], a[1]);
                *(float2*)(dst + (size_t)(m + 8) * 256 + col) = make_float2(a[2], a[3]);
            }
        }
    }
}

// ---------------------------------------------------------------------------
// helper: warp-lane L2 normalization of a 32-wide head chunk value
// ---------------------------------------------------------------------------
__device__ __forceinline__ float l2n(float v) {
    float ss = v * v;
    #pragma unroll
    for (int o = 16; o; o >>= 1) ss += __shfl_xor_sync(0xffffffffu, ss, o);
    return v / fmaxf(sqrtf(ss), 1e-12f);
}

// ---------------------------------------------------------------------------
// Spatial linear attention (attend over N=2048), l2norm fused into loads.
// One block (8 warps) per (bt, h).
// ---------------------------------------------------------------------------
__global__ __launch_bounds__(256)
void spatial_attn_kernel(const float* __restrict__ q, const float* __restrict__ k,
                         const float* __restrict__ v, float* __restrict__ o)
{
    const int bt = blockIdx.x;
    const int h  = blockIdx.y;
    const int tid = threadIdx.x;
    const int w = tid >> 5, lane = tid & 31;

    __shared__ float kvs[32][33];
    __shared__ float kss[32];
    for (int i = tid; i < 32 * 33; i += 256) (&kvs[0][0])[i] = 0.f;
    if (tid < 32) kss[tid] = 0.f;
    __syncthreads();

    const size_t baseBT = (size_t)bt * N_ * D_ + h * HD_;

    float acc[32];
    #pragma unroll
    for (int m = 0; m < 32; m++) acc[m] = 0.f;
    float ksd = 0.f;

    for (int l = w; l < N_; l += 8) {
        size_t off = baseBT + (size_t)l * D_ + lane;
        float kd = l2n(k[off]);
        float vd = v[off];
        ksd += kd;
        #pragma unroll
        for (int m = 0; m < 32; m++)
            acc[m] = fmaf(__shfl_sync(0xffffffffu, kd, m), vd, acc[m]);
    }
    #pragma unroll
    for (int m = 0; m < 32; m++) atomicAdd(&kvs[m][lane], acc[m]);
    atomicAdd(&kss[lane], ksd);
    __syncthreads();

    const float kssd = kss[lane];
    for (int l = w; l < N_; l += 8) {
        size_t off = baseBT + (size_t)l * D_ + lane;
        float qd = l2n(q[off]);
        float vd = v[off];
        float den = qd * kssd;
        #pragma unroll
        for (int o2 = 16; o2; o2 >>= 1) den += __shfl_xor_sync(0xffffffffu, den, o2);
        den = fmaxf(den + (float)N_, 1e-5f);
        float num = (float)N_ * vd;
        #pragma unroll
        for (int m = 0; m < 32; m++)
            num = fmaf(__shfl_sync(0xffffffffu, qd, m), kvs[m][lane], num);
        o[off] = num / den;
    }
}

// ---------------------------------------------------------------------------
// Temporal linear attention (attend over T=24), l2norm fused into loads.
// One block per (b, n); warp = head.
// ---------------------------------------------------------------------------
__global__ __launch_bounds__(256)
void temporal_attn_kernel(const float* __restrict__ q, const float* __restrict__ k,
                          const float* __restrict__ v, float* __restrict__ o)
{
    const int bn = blockIdx.x;
    const int b = bn >> 11;
    const int n = bn & 2047;
    const int tid = threadIdx.x;
    const int h = tid >> 5, lane = tid & 31;

    const size_t base = ((size_t)b * T_ * N_ + n) * D_ + h * HD_ + lane;
    const size_t strideT = (size_t)N_ * D_;

    float acc[32];
    #pragma unroll
    for (int m = 0; m < 32; m++) acc[m] = 0.f;
    float vreg[T_];
    float ksd = 0.f;

    #pragma unroll
    for (int t = 0; t < T_; t++) {
        size_t off = base + (size_t)t * strideT;
        float kd = l2n(k[off]);
        float vd = v[off];
        vreg[t] = vd;
        ksd += kd;
        #pragma unroll
        for (int m = 0; m < 32; m++)
            acc[m] = fmaf(__shfl_sync(0xffffffffu, kd, m), vd, acc[m]);
    }

    #pragma unroll
    for (int t = 0; t < T_; t++) {
        size_t off = base + (size_t)t * strideT;
        float qd = l2n(q[off]);
        float den = qd * ksd;
        #pragma unroll
        for (int o2 = 16; o2; o2 >>= 1) den += __shfl_xor_sync(0xffffffffu, den, o2);
        den = fmaxf(den + (float)T_, 1e-5f);
        float num = (float)T_ * vreg[t];
        #pragma unroll
        for (int m = 0; m < 32; m++)
            num = fmaf(__shfl_sync(0xffffffffu, qd, m), acc[m], num);
        o[off] = num / den;
    }
}

// ---------------------------------------------------------------------------
extern "C" void kernel_launch(void* const* d_in, const int* in_sizes, int n_in,
                              void* d_out, int out_size)
{
    const float* x     = (const float*)d_in[0];
    const float* w_qkv = (const float*)d_in[1];
    const float* w_out = (const float*)d_in[2];
    const float* b_out = (const float*)d_in[3];
    float* out = (float*)d_out;

    float *q, *k, *v, *os, *ot;
    cudaGetSymbolAddress((void**)&q,  g_q);
    cudaGetSymbolAddress((void**)&k,  g_k);
    cudaGetSymbolAddress((void**)&v,  g_v);
    cudaGetSymbolAddress((void**)&os, g_os);
    cudaGetSymbolAddress((void**)&ot, g_ot);

    cudaFuncSetAttribute(mma_gemm<256, false, false>,
                         cudaFuncAttributeMaxDynamicSharedMemorySize, SMEM_BYTES);
    cudaFuncSetAttribute(mma_gemm<512, true, true>,
                         cudaFuncAttributeMaxDynamicSharedMemorySize, SMEM_BYTES);

    // 1) QKV projection (tf32 tensor cores), scatter into q/k/v
    {
        dim3 grid(6, MTOK / 128);
        mma_gemm<256, false, false><<<grid, 256, SMEM_BYTES>>>(
            x, nullptr, w_qkv, 256, nullptr, q, k, v);
    }
    // 2) spatial attention (l2norm fused)
    {
        dim3 grid(B_ * T_, H_);
        spatial_attn_kernel<<<grid, 256>>>(q, k, v, os);
    }
    // 3) temporal attention (l2norm fused)
    {
        temporal_attn_kernel<<<B_ * N_, 256>>>(q, k, v, ot);
    }
    // 4) output projection + bias (tf32 tensor cores, dual-A concat)
    {
        dim3 grid(2, MTOK / 128);
        mma_gemm<512, true, true><<<grid, 256, SMEM_BYTES>>>(
            os, ot, w_out, 512, b_out, out, nullptr, nullptr);
    }
}

// round 3
// speedup vs baseline: 2.4311x; 1.7718x over previous
#include <cuda_runtime.h>
#include <math.h>
#include <stdint.h>

#define B_  4
#define T_  24
#define N_  2048
#define D_  256
#define H_  8
#define HD_ 32
#define MTOK (B_*T_*N_)           // 196608 tokens
#define ELEMS ((size_t)MTOK * D_) // 50,331,648

// Scratch (device globals; allocation-free per harness rules)
__device__ float g_q [ELEMS];
__device__ float g_k [ELEMS];
__device__ float g_v [ELEMS];
__device__ float g_os[ELEMS];
__device__ float g_ot[ELEMS];

// ---------------------------------------------------------------------------
// tf32 mma.sync GEMM: C[M,N] = A[M,K]*B[N,K]^T  (both K-contiguous, "TN")
// CTA tile 128x128x32, 256 threads = 8 warps (2 m x 4 n), warp tile 64x32.
// NORM: fused per-32-col-chunk L2 normalization in epilogue (q/k outputs).
// ---------------------------------------------------------------------------
#define GBK   32
#define KBWRD 1026                 // words per k-block (128*8 + 2 pad)
#define OPWRD (4*KBWRD)            // words per operand per buffer = 4104
#define SMEM_BYTES (2*2*OPWRD*4)   // 65664

__device__ __forceinline__ uint32_t f2tf32(float f) {
    uint32_t u;
    asm("cvt.rna.tf32.f32 %0, %1;" : "=r"(u) : "f"(f));
    return u;
}

#define MMA_TF32(d, a0, a1, a2, a3, b0, b1)                                   \
    asm volatile("mma.sync.aligned.m16n8k8.row.col.f32.tf32.tf32.f32 "        \
                 "{%0,%1,%2,%3}, {%4,%5,%6,%7}, {%8,%9}, {%0,%1,%2,%3};"      \
                 : "+f"(d[0]), "+f"(d[1]), "+f"(d[2]), "+f"(d[3])             \
                 : "r"(a0), "r"(a1), "r"(a2), "r"(a3), "r"(b0), "r"(b1))

template<int KTOT, bool DUAL, bool BIAS, bool NORM>
__global__ __launch_bounds__(256, 1)
void mma_gemm(const float* __restrict__ A0, const float* __restrict__ A1,
              const float* __restrict__ Bw, int ldb,
              const float* __restrict__ bias,
              float* __restrict__ o0, float* __restrict__ o1,
              float* __restrict__ o2)
{
    extern __shared__ uint32_t sh[];
    const int tid  = threadIdx.x;
    const int lane = tid & 31;
    const int wid  = tid >> 5;
    const int wm   = wid & 1;
    const int wn   = wid >> 1;
    const int m0   = blockIdx.y * 128;
    const int n0g  = blockIdx.x * 128;

    const int kq    = tid & 7;
    const int rbase = tid >> 3;
    const int kb    = kq >> 1;
    const int par   = kq & 1;
    const int xr    = (rbase & 3) << 1;

    const int r   = lane >> 2;
    const int cx  = ((lane & 3) << 1) ^ ((r & 3) << 1);

    float acc[4][4][4];
    #pragma unroll
    for (int i = 0; i < 4; i++)
        #pragma unroll
        for (int j = 0; j < 4; j++)
            #pragma unroll
            for (int c = 0; c < 4; c++) acc[i][j][c] = 0.f;

    float4 sA[4], sB[4];
    const int KT = KTOT / GBK;

    auto load_tiles = [&](int kt) {
        const int k0 = kt * GBK;
        #pragma unroll
        for (int i = 0; i < 4; i++) {
            int row = rbase + 32 * i;
            const float* pa;
            if (DUAL) {
                int kg = k0 + kq * 4;
                pa = (kg < 256) ? (A0 + (size_t)(m0 + row) * 256 + kg)
                                : (A1 + (size_t)(m0 + row) * 256 + (kg - 256));
            } else {
                pa = A0 + (size_t)(m0 + row) * KTOT + k0 + kq * 4;
            }
            sA[i] = *(const float4*)pa;
            sB[i] = *(const float4*)(Bw + (size_t)(n0g + row) * ldb + k0 + kq * 4);
        }
    };

    auto store_tiles = [&](int buf) {
        uint32_t* sa = sh + buf * 2 * OPWRD;
        uint32_t* sb = sa + OPWRD;
        #pragma unroll
        for (int i = 0; i < 4; i++) {
            int row  = rbase + 32 * i;
            int base = kb * KBWRD + row * 8;
            sa[base + (((0 << 1) | par) ^ xr)] = f2tf32(sA[i].x);
            sa[base + (((1 << 1) | par) ^ xr)] = f2tf32(sA[i].y);
            sa[base + (((2 << 1) | par) ^ xr)] = f2tf32(sA[i].z);
            sa[base + (((3 << 1) | par) ^ xr)] = f2tf32(sA[i].w);
            sb[base + (((0 << 1) | par) ^ xr)] = f2tf32(sB[i].x);
            sb[base + (((1 << 1) | par) ^ xr)] = f2tf32(sB[i].y);
            sb[base + (((2 << 1) | par) ^ xr)] = f2tf32(sB[i].z);
            sb[base + (((3 << 1) | par) ^ xr)] = f2tf32(sB[i].w);
        }
    };

    auto compute = [&](int buf) {
        const uint32_t* sa = sh + buf * 2 * OPWRD;
        const uint32_t* sb = sa + OPWRD;
        #pragma unroll
        for (int kk = 0; kk < 4; kk++) {
            uint2 bf[4];
            #pragma unroll
            for (int nt = 0; nt < 4; nt++) {
                int n = wn * 32 + nt * 8 + r;
                bf[nt] = *(const uint2*)&sb[kk * KBWRD + n * 8 + cx];
            }
            uint2 alo[4], ahi[4];
            #pragma unroll
            for (int mt = 0; mt < 4; mt++) {
                int row = wm * 64 + mt * 16 + r;
                alo[mt] = *(const uint2*)&sa[kk * KBWRD + row * 8 + cx];
                ahi[mt] = *(const uint2*)&sa[kk * KBWRD + (row + 8) * 8 + cx];
            }
            #pragma unroll
            for (int mt = 0; mt < 4; mt++)
                #pragma unroll
                for (int nt = 0; nt < 4; nt++)
                    MMA_TF32(acc[mt][nt], alo[mt].x, ahi[mt].x,
                             alo[mt].y, ahi[mt].y, bf[nt].x, bf[nt].y);
        }
    };

    load_tiles(0);
    store_tiles(0);
    __syncthreads();
    for (int kt = 0; kt < KT; kt++) {
        if (kt + 1 < KT) load_tiles(kt + 1);
        compute(kt & 1);
        if (kt + 1 < KT) store_tiles((kt + 1) & 1);
        __syncthreads();
    }

    const int sel = n0g >> 8;

    // fused L2 normalization: each lane-quad (lane^1, lane^2) holds the full
    // 32-col head chunk for its two rows; normalize q (sel 0) and k (sel 1).
    if (NORM && sel < 2) {
        #pragma unroll
        for (int mt = 0; mt < 4; mt++) {
            float sslo = 0.f, sshi = 0.f;
            #pragma unroll
            for (int nt = 0; nt < 4; nt++) {
                sslo = fmaf(acc[mt][nt][0], acc[mt][nt][0], sslo);
                sslo = fmaf(acc[mt][nt][1], acc[mt][nt][1], sslo);
                sshi = fmaf(acc[mt][nt][2], acc[mt][nt][2], sshi);
                sshi = fmaf(acc[mt][nt][3], acc[mt][nt][3], sshi);
            }
            sslo += __shfl_xor_sync(0xffffffffu, sslo, 1);
            sslo += __shfl_xor_sync(0xffffffffu, sslo, 2);
            sshi += __shfl_xor_sync(0xffffffffu, sshi, 1);
            sshi += __shfl_xor_sync(0xffffffffu, sshi, 2);
            float slo = 1.f / fmaxf(sqrtf(sslo), 1e-12f);
            float shi = 1.f / fmaxf(sqrtf(sshi), 1e-12f);
            #pragma unroll
            for (int nt = 0; nt < 4; nt++) {
                acc[mt][nt][0] *= slo; acc[mt][nt][1] *= slo;
                acc[mt][nt][2] *= shi; acc[mt][nt][3] *= shi;
            }
        }
    }

    const int c2 = (lane & 3) << 1;
    #pragma unroll
    for (int mt = 0; mt < 4; mt++) {
        int m = m0 + wm * 64 + mt * 16 + r;
        #pragma unroll
        for (int nt = 0; nt < 4; nt++) {
            int n = n0g + wn * 32 + nt * 8 + c2;
            float* a = acc[mt][nt];
            if (BIAS) {
                float b0 = bias[n], b1 = bias[n + 1];
                *(float2*)(o0 + (size_t)m * 256 + n)       = make_float2(a[0] + b0, a[1] + b1);
                *(float2*)(o0 + (size_t)(m + 8) * 256 + n) = make_float2(a[2] + b0, a[3] + b1);
            } else {
                float* dst = (sel == 0) ? o0 : ((sel == 1) ? o1 : o2);
                int col = n & 255;
                *(float2*)(dst + (size_t)m * 256 + col)       = make_float2(a[0], a[1]);
                *(float2*)(dst + (size_t)(m + 8) * 256 + col) = make_float2(a[2], a[3]);
            }
        }
    }
}

// ---------------------------------------------------------------------------
// Spatial linear attention (attend over N=2048). Block = (bt, h), 8 warps.
// Phase 1: per-warp kvs partials with 4m x 8d register tiles (no shfl),
//          cross-warp smem reduction. Phase 2: smem GEMM with 8l x 4d tiles.
// q, k are pre-normalized (GEMM1 epilogue).
// ---------------------------------------------------------------------------
#define SQS 36
__global__ __launch_bounds__(256)
void spatial_attn_kernel(const float* __restrict__ q, const float* __restrict__ k,
                         const float* __restrict__ v, float* __restrict__ o)
{
    __shared__ float s_part[8][32][SQS];   // phase1 partials; phase2: per-warp q stage
    __shared__ float s_kvs[32][SQS];
    __shared__ float s_ksp[8][32];
    __shared__ float s_kss[32];

    const int bt = blockIdx.x;
    const int h  = blockIdx.y;
    const int tid = threadIdx.x;
    const int w = tid >> 5, lane = tid & 31;

    const size_t baseBT = (size_t)bt * N_ * D_ + h * HD_;

    // ---- phase 1 ----
    const int mg = lane >> 2;       // m = mg*4 + i
    const int dg = lane & 3;        // d = dg*8 + j
    float acc[4][8] = {};
    float kss[4] = {0.f, 0.f, 0.f, 0.f};

    const int l0w = w * 256;
    #pragma unroll 4
    for (int l = l0w; l < l0w + 256; l++) {
        const float* rk = k + baseBT + (size_t)l * D_;
        const float* rv = v + baseBT + (size_t)l * D_;
        float4 kf = *(const float4*)(rk + mg * 4);
        float4 va = *(const float4*)(rv + dg * 8);
        float4 vb = *(const float4*)(rv + dg * 8 + 4);
        float kk[4] = {kf.x, kf.y, kf.z, kf.w};
        float vv[8] = {va.x, va.y, va.z, va.w, vb.x, vb.y, vb.z, vb.w};
        #pragma unroll
        for (int i = 0; i < 4; i++) {
            kss[i] += kk[i];
            #pragma unroll
            for (int j = 0; j < 8; j++)
                acc[i][j] = fmaf(kk[i], vv[j], acc[i][j]);
        }
    }
    #pragma unroll
    for (int i = 0; i < 4; i++) {
        *(float4*)&s_part[w][mg*4+i][dg*8]     = make_float4(acc[i][0], acc[i][1], acc[i][2], acc[i][3]);
        *(float4*)&s_part[w][mg*4+i][dg*8 + 4] = make_float4(acc[i][4], acc[i][5], acc[i][6], acc[i][7]);
    }
    if (dg == 0) {
        #pragma unroll
        for (int i = 0; i < 4; i++) s_ksp[w][mg*4+i] = kss[i];
    }
    __syncthreads();

    // ---- reduce partials ----
    {
        int m = tid >> 3, dd = (tid & 7) * 4;
        float4 s = make_float4(0.f, 0.f, 0.f, 0.f);
        #pragma unroll
        for (int wi = 0; wi < 8; wi++) {
            float4 p = *(const float4*)&s_part[wi][m][dd];
            s.x += p.x; s.y += p.y; s.z += p.z; s.w += p.w;
        }
        *(float4*)&s_kvs[m][dd] = s;
        if (tid < 32) {
            float s2 = 0.f;
            #pragma unroll
            for (int wi = 0; wi < 8; wi++) s2 += s_ksp[wi][tid];
            s_kss[tid] = s2;
        }
    }
    __syncthreads();

    // ---- phase 2 ----
    float* qs = &s_part[w][0][0];     // per-warp [32][SQS] q stage (aliased)
    const int lg = lane >> 3;         // l = l0 + i*4 + lg
    const int d4 = (lane & 7) * 4;

    for (int c = 0; c < 8; c++) {
        const int l0 = l0w + c * 32;
        #pragma unroll
        for (int i2 = 0; i2 < 8; i2++) {
            int idx = lane + i2 * 32;       // 0..255
            int rr = idx >> 3, f = idx & 7;
            *(float4*)(qs + rr * SQS + f * 4) =
                *(const float4*)(q + baseBT + (size_t)(l0 + rr) * D_ + f * 4);
        }
        __syncwarp();

        float num[8][4] = {};
        float den[8] = {};
        #pragma unroll
        for (int m = 0; m < 32; m++) {
            float km = s_kss[m];
            float4 kr = *(const float4*)&s_kvs[m][d4];
            #pragma unroll
            for (int i = 0; i < 8; i++) {
                float qm = qs[(i * 4 + lg) * SQS + m];
                den[i] = fmaf(qm, km, den[i]);
                num[i][0] = fmaf(qm, kr.x, num[i][0]);
                num[i][1] = fmaf(qm, kr.y, num[i][1]);
                num[i][2] = fmaf(qm, kr.z, num[i][2]);
                num[i][3] = fmaf(qm, kr.w, num[i][3]);
            }
        }
        #pragma unroll
        for (int i = 0; i < 8; i++) {
            int l = l0 + i * 4 + lg;
            float4 vf = *(const float4*)(v + baseBT + (size_t)l * D_ + d4);
            float ddn = fmaxf(den[i] + (float)N_, 1e-5f);
            float inv = 1.f / ddn;
            float4 rr;
            rr.x = (num[i][0] + (float)N_ * vf.x) * inv;
            rr.y = (num[i][1] + (float)N_ * vf.y) * inv;
            rr.z = (num[i][2] + (float)N_ * vf.z) * inv;
            rr.w = (num[i][3] + (float)N_ * vf.w) * inv;
            *(float4*)(o + baseBT + (size_t)l * D_ + d4) = rr;
        }
        __syncwarp();
    }
}

// ---------------------------------------------------------------------------
// Temporal linear attention (attend over T=24). Block = (b, n), warp = head.
// Fully warp-independent: register-tiled kvs (4m x 8d), smem round-trip,
// phase-2 6t x 4d register tiles. q, k pre-normalized.
// ---------------------------------------------------------------------------
#define TSM_KVS (8*32*SQS)
#define TSM_Q   (8*24*SQS)
#define TSM_BYTES ((TSM_KVS + TSM_Q + 8*32) * 4)   // 65536
__global__ __launch_bounds__(256)
void temporal_attn_kernel(const float* __restrict__ q, const float* __restrict__ k,
                          const float* __restrict__ v, float* __restrict__ o)
{
    extern __shared__ float sm[];
    const int bn = blockIdx.x;
    const int b = bn >> 11;
    const int n = bn & 2047;
    const int tid = threadIdx.x;
    const int h = tid >> 5, lane = tid & 31;

    float* kvs_h = sm + h * 32 * SQS;
    float* q_h   = sm + TSM_KVS + h * 24 * SQS;
    float* kss_h = sm + TSM_KVS + TSM_Q + h * 32;

    const size_t base = ((size_t)b * T_ * N_ + n) * D_ + h * HD_;
    const size_t sT = (size_t)N_ * D_;

    // ---- phase 1 ----
    const int mg = lane >> 2;
    const int dg = lane & 3;
    float acc[4][8] = {};
    float kss[4] = {0.f, 0.f, 0.f, 0.f};

    #pragma unroll
    for (int t = 0; t < T_; t++) {
        const float* rk = k + base + (size_t)t * sT;
        const float* rv = v + base + (size_t)t * sT;
        float4 kf = *(const float4*)(rk + mg * 4);
        float4 va = *(const float4*)(rv + dg * 8);
        float4 vb = *(const float4*)(rv + dg * 8 + 4);
        float kk[4] = {kf.x, kf.y, kf.z, kf.w};
        float vv[8] = {va.x, va.y, va.z, va.w, vb.x, vb.y, vb.z, vb.w};
        #pragma unroll
        for (int i = 0; i < 4; i++) {
            kss[i] += kk[i];
            #pragma unroll
            for (int j = 0; j < 8; j++)
                acc[i][j] = fmaf(kk[i], vv[j], acc[i][j]);
        }
    }
    #pragma unroll
    for (int i = 0; i < 4; i++) {
        *(float4*)(kvs_h + (mg*4+i) * SQS + dg*8)     = make_float4(acc[i][0], acc[i][1], acc[i][2], acc[i][3]);
        *(float4*)(kvs_h + (mg*4+i) * SQS + dg*8 + 4) = make_float4(acc[i][4], acc[i][5], acc[i][6], acc[i][7]);
    }
    if (dg == 0) {
        #pragma unroll
        for (int i = 0; i < 4; i++) kss_h[mg*4+i] = kss[i];
    }
    // stage q (24 rows x 32 cols = 192 float4)
    #pragma unroll
    for (int i = 0; i < 6; i++) {
        int idx = lane + i * 32;
        int t = idx >> 3, f = idx & 7;
        *(float4*)(q_h + t * SQS + f * 4) =
            *(const float4*)(q + base + (size_t)t * sT + f * 4);
    }
    __syncwarp();

    // ---- phase 2: lane tile 6t x 4d ----
    const int tg = lane >> 3;
    const int d4 = (lane & 7) * 4;
    float num[6][4] = {};
    float den[6] = {};
    #pragma unroll
    for (int m = 0; m < 32; m++) {
        float km = kss_h[m];
        float4 kr = *(const float4*)(kvs_h + m * SQS + d4);
        #pragma unroll
        for (int i = 0; i < 6; i++) {
            float qm = q_h[(tg * 6 + i) * SQS + m];
            den[i] = fmaf(qm, km, den[i]);
            num[i][0] = fmaf(qm, kr.x, num[i][0]);
            num[i][1] = fmaf(qm, kr.y, num[i][1]);
            num[i][2] = fmaf(qm, kr.z, num[i][2]);
            num[i][3] = fmaf(qm, kr.w, num[i][3]);
        }
    }
    #pragma unroll
    for (int i = 0; i < 6; i++) {
        int t = tg * 6 + i;
        float4 vf = *(const float4*)(v + base + (size_t)t * sT + d4);
        float ddn = fmaxf(den[i] + (float)T_, 1e-5f);
        float inv = 1.f / ddn;
        float4 rr;
        rr.x = (num[i][0] + (float)T_ * vf.x) * inv;
        rr.y = (num[i][1] + (float)T_ * vf.y) * inv;
        rr.z = (num[i][2] + (float)T_ * vf.z) * inv;
        rr.w = (num[i][3] + (float)T_ * vf.w) * inv;
        *(float4*)(o + base + (size_t)t * sT + d4) = rr;
    }
}

// ---------------------------------------------------------------------------
extern "C" void kernel_launch(void* const* d_in, const int* in_sizes, int n_in,
                              void* d_out, int out_size)
{
    const float* x     = (const float*)d_in[0];
    const float* w_qkv = (const float*)d_in[1];
    const float* w_out = (const float*)d_in[2];
    const float* b_out = (const float*)d_in[3];
    float* out = (float*)d_out;

    float *q, *k, *v, *os, *ot;
    cudaGetSymbolAddress((void**)&q,  g_q);
    cudaGetSymbolAddress((void**)&k,  g_k);
    cudaGetSymbolAddress((void**)&v,  g_v);
    cudaGetSymbolAddress((void**)&os, g_os);
    cudaGetSymbolAddress((void**)&ot, g_ot);

    cudaFuncSetAttribute(mma_gemm<256, false, false, true>,
                         cudaFuncAttributeMaxDynamicSharedMemorySize, SMEM_BYTES);
    cudaFuncSetAttribute(mma_gemm<512, true, true, false>,
                         cudaFuncAttributeMaxDynamicSharedMemorySize, SMEM_BYTES);
    cudaFuncSetAttribute(temporal_attn_kernel,
                         cudaFuncAttributeMaxDynamicSharedMemorySize, TSM_BYTES);

    // 1) QKV projection (tf32) with fused q/k L2-normalization
    {
        dim3 grid(6, MTOK / 128);
        mma_gemm<256, false, false, true><<<grid, 256, SMEM_BYTES>>>(
            x, nullptr, w_qkv, 256, nullptr, q, k, v);
    }
    // 2) spatial attention
    {
        dim3 grid(B_ * T_, H_);
        spatial_attn_kernel<<<grid, 256>>>(q, k, v, os);
    }
    // 3) temporal attention
    {
        temporal_attn_kernel<<<B_ * N_, 256, TSM_BYTES>>>(q, k, v, ot);
    }
    // 4) output projection + bias (tf32, dual-A concat)
    {
        dim3 grid(2, MTOK / 128);
        mma_gemm<512, true, true, false><<<grid, 256, SMEM_BYTES>>>(
            os, ot, w_out, 512, b_out, out, nullptr, nullptr);
    }
}

// round 5
// speedup vs baseline: 2.4701x; 1.0160x over previous
#include <cuda_runtime.h>
#include <math.h>
#include <stdint.h>

#define B_  4
#define T_  24
#define N_  2048
#define D_  256
#define H_  8
#define HD_ 32
#define MTOK (B_*T_*N_)           // 196608 tokens
#define ELEMS ((size_t)MTOK * D_) // 50,331,648

// Scratch (device globals; allocation-free per harness rules)
__device__ float g_q [ELEMS];
__device__ float g_k [ELEMS];
__device__ float g_v [ELEMS];
__device__ float g_os[ELEMS];
__device__ float g_ot[ELEMS];

// ---------------------------------------------------------------------------
// Common tf32 mma helpers. SMEM layout per 32-k chunk: 4 k-blocks of 8 k's,
// each block [128 rows][8 words], k permuted s=(k&3)*2|(k>>2&1), XOR (row&3)<<1.
// Block stride 1026 words (2-word pad).
// ---------------------------------------------------------------------------
#define KBWRD 1026
#define BWRD  (4*KBWRD)            // words per operand per 32-k chunk = 4104

__device__ __forceinline__ uint32_t f2tf32(float f) {
    uint32_t u;
    asm("cvt.rna.tf32.f32 %0, %1;" : "=r"(u) : "f"(f));
    return u;
}

#define MMA_TF32(d, a0, a1, a2, a3, b0, b1)                                   \
    asm volatile("mma.sync.aligned.m16n8k8.row.col.f32.tf32.tf32.f32 "        \
                 "{%0,%1,%2,%3}, {%4,%5,%6,%7}, {%8,%9}, {%0,%1,%2,%3};"      \
                 : "+f"(d[0]), "+f"(d[1]), "+f"(d[2]), "+f"(d[3])             \
                 : "r"(a0), "r"(a1), "r"(a2), "r"(a3), "r"(b0), "r"(b1))

// ===========================================================================
// GEMM1 (A-resident): qkv[M,768] = x[M,256] * w_qkv[768,256]^T
// One CTA per 128 rows of x. Full A tile (128x256 tf32) resident in smem;
// loop over 6 n-tiles x 8 k-chunks with double-buffered B. Fused q/k l2norm.
// ===========================================================================
#define AWRD (32*KBWRD)                       // 32 k-blocks (full K=256)
#define G1_SMEM ((AWRD + 2*BWRD)*4)           // 164160 bytes

__global__ __launch_bounds__(256, 1)
void gemm_qkv_kernel(const float* __restrict__ A, const float* __restrict__ Bw,
                     float* __restrict__ outq, float* __restrict__ outk,
                     float* __restrict__ outv)
{
    extern __shared__ uint32_t sh[];
    uint32_t* sA = sh;                        // resident A
    const int tid  = threadIdx.x;
    const int lane = tid & 31;
    const int wid  = tid >> 5;
    const int wm   = wid & 1;                 // m offset wm*64
    const int wn   = wid >> 1;                // n offset wn*32
    const int m0   = blockIdx.x * 128;

    const int kq    = tid & 7;
    const int rbase = tid >> 3;
    const int kb    = kq >> 1;
    const int par   = kq & 1;
    const int xr    = (rbase & 3) << 1;

    const int r   = lane >> 2;
    const int cx  = ((lane & 3) << 1) ^ ((r & 3) << 1);

    // ---- prologue: A (128x256) -> smem (converted + swizzled), once ----
    #pragma unroll
    for (int kt = 0; kt < 8; kt++) {
        #pragma unroll
        for (int i = 0; i < 4; i++) {
            int row = rbase + 32 * i;
            float4 a = *(const float4*)(A + (size_t)(m0 + row) * 256 + kt * 32 + kq * 4);
            int base = (kt * 4 + kb) * KBWRD + row * 8;
            sA[base + (((0 << 1) | par) ^ xr)] = f2tf32(a.x);
            sA[base + (((1 << 1) | par) ^ xr)] = f2tf32(a.y);
            sA[base + (((2 << 1) | par) ^ xr)] = f2tf32(a.z);
            sA[base + (((3 << 1) | par) ^ xr)] = f2tf32(a.w);
        }
    }

    float4 rB[4];
    auto ldgB = [&](int it) {
        const int nt = it >> 3, kt = it & 7;
        #pragma unroll
        for (int i = 0; i < 4; i++) {
            int row = rbase + 32 * i;
            rB[i] = *(const float4*)(Bw + (size_t)(nt * 128 + row) * 256 + kt * 32 + kq * 4);
        }
    };
    auto stsB = [&](int buf) {
        uint32_t* sb = sh + AWRD + buf * BWRD;
        #pragma unroll
        for (int i = 0; i < 4; i++) {
            int row  = rbase + 32 * i;
            int base = kb * KBWRD + row * 8;
            sb[base + (((0 << 1) | par) ^ xr)] = f2tf32(rB[i].x);
            sb[base + (((1 << 1) | par) ^ xr)] = f2tf32(rB[i].y);
            sb[base + (((2 << 1) | par) ^ xr)] = f2tf32(rB[i].z);
            sb[base + (((3 << 1) | par) ^ xr)] = f2tf32(rB[i].w);
        }
    };

    float acc[4][4][4];
    #pragma unroll
    for (int i = 0; i < 4; i++)
        #pragma unroll
        for (int j = 0; j < 4; j++)
            #pragma unroll
            for (int c = 0; c < 4; c++) acc[i][j][c] = 0.f;

    ldgB(0);
    stsB(0);
    __syncthreads();

    const int c2 = (lane & 3) << 1;

    #pragma unroll 1
    for (int it = 0; it < 48; it++) {
        if (it + 1 < 48) ldgB(it + 1);

        // ---- compute: A chunk (it&7), B buffer (it&1) ----
        {
            const uint32_t* sa = sh + (it & 7) * 4 * KBWRD;
            const uint32_t* sb = sh + AWRD + (it & 1) * BWRD;
            #pragma unroll
            for (int kk = 0; kk < 4; kk++) {
                uint2 bf[4];
                #pragma unroll
                for (int nt2 = 0; nt2 < 4; nt2++) {
                    int n = wn * 32 + nt2 * 8 + r;
                    bf[nt2] = *(const uint2*)&sb[kk * KBWRD + n * 8 + cx];
                }
                uint2 alo[4], ahi[4];
                #pragma unroll
                for (int mt = 0; mt < 4; mt++) {
                    int row = wm * 64 + mt * 16 + r;
                    alo[mt] = *(const uint2*)&sa[kk * KBWRD + row * 8 + cx];
                    ahi[mt] = *(const uint2*)&sa[kk * KBWRD + (row + 8) * 8 + cx];
                }
                #pragma unroll
                for (int mt = 0; mt < 4; mt++)
                    #pragma unroll
                    for (int nt2 = 0; nt2 < 4; nt2++)
                        MMA_TF32(acc[mt][nt2], alo[mt].x, ahi[mt].x,
                                 alo[mt].y, ahi[mt].y, bf[nt2].x, bf[nt2].y);
            }
        }

        // ---- per-n-tile epilogue ----
        if ((it & 7) == 7) {
            const int ntile = it >> 3;
            const int n0g   = ntile * 128;
            const int sel   = n0g >> 8;

            if (sel < 2) {   // q or k: fused per-head L2 norm
                #pragma unroll
                for (int mt = 0; mt < 4; mt++) {
                    float sslo = 0.f, sshi = 0.f;
                    #pragma unroll
                    for (int nt2 = 0; nt2 < 4; nt2++) {
                        sslo = fmaf(acc[mt][nt2][0], acc[mt][nt2][0], sslo);
                        sslo = fmaf(acc[mt][nt2][1], acc[mt][nt2][1], sslo);
                        sshi = fmaf(acc[mt][nt2][2], acc[mt][nt2][2], sshi);
                        sshi = fmaf(acc[mt][nt2][3], acc[mt][nt2][3], sshi);
                    }
                    sslo += __shfl_xor_sync(0xffffffffu, sslo, 1);
                    sslo += __shfl_xor_sync(0xffffffffu, sslo, 2);
                    sshi += __shfl_xor_sync(0xffffffffu, sshi, 1);
                    sshi += __shfl_xor_sync(0xffffffffu, sshi, 2);
                    float slo = 1.f / fmaxf(sqrtf(sslo), 1e-12f);
                    float shi = 1.f / fmaxf(sqrtf(sshi), 1e-12f);
                    #pragma unroll
                    for (int nt2 = 0; nt2 < 4; nt2++) {
                        acc[mt][nt2][0] *= slo; acc[mt][nt2][1] *= slo;
                        acc[mt][nt2][2] *= shi; acc[mt][nt2][3] *= shi;
                    }
                }
            }

            float* dst = (sel == 0) ? outq : ((sel == 1) ? outk : outv);
            #pragma unroll
            for (int mt = 0; mt < 4; mt++) {
                int m = m0 + wm * 64 + mt * 16 + r;
                #pragma unroll
                for (int nt2 = 0; nt2 < 4; nt2++) {
                    int col = ((n0g + wn * 32 + nt2 * 8 + c2) & 255);
                    float* a = acc[mt][nt2];
                    *(float2*)(dst + (size_t)m * 256 + col)       = make_float2(a[0], a[1]);
                    *(float2*)(dst + (size_t)(m + 8) * 256 + col) = make_float2(a[2], a[3]);
                    a[0] = a[1] = a[2] = a[3] = 0.f;
                }
            }
        }

        if (it + 1 < 48) stsB((it + 1) & 1);
        __syncthreads();
    }
}

// ===========================================================================
// GEMM2: out[M,256] = [os|ot][M,512] * w_out[256,512]^T + b  (round-3 kernel)
// ===========================================================================
#define OPWRD (4*KBWRD)
#define G2_SMEM (2*2*OPWRD*4)      // 65664

__global__ __launch_bounds__(256, 1)
void gemm_out_kernel(const float* __restrict__ A0, const float* __restrict__ A1,
                     const float* __restrict__ Bw,
                     const float* __restrict__ bias,
                     float* __restrict__ out)
{
    extern __shared__ uint32_t sh[];
    const int tid  = threadIdx.x;
    const int lane = tid & 31;
    const int wid  = tid >> 5;
    const int wm   = wid & 1;
    const int wn   = wid >> 1;
    const int m0   = blockIdx.y * 128;
    const int n0g  = blockIdx.x * 128;

    const int kq    = tid & 7;
    const int rbase = tid >> 3;
    const int kb    = kq >> 1;
    const int par   = kq & 1;
    const int xr    = (rbase & 3) << 1;

    const int r   = lane >> 2;
    const int cx  = ((lane & 3) << 1) ^ ((r & 3) << 1);

    float acc[4][4][4];
    #pragma unroll
    for (int i = 0; i < 4; i++)
        #pragma unroll
        for (int j = 0; j < 4; j++)
            #pragma unroll
            for (int c = 0; c < 4; c++) acc[i][j][c] = 0.f;

    float4 sAr[4], sBr[4];

    auto load_tiles = [&](int kt) {
        const int k0 = kt * 32;
        const int kg = k0 + kq * 4;
        const float* Asrc = (kg < 256) ? A0 : A1;
        const int kc = kg & 255;
        #pragma unroll
        for (int i = 0; i < 4; i++) {
            int row = rbase + 32 * i;
            sAr[i] = *(const float4*)(Asrc + (size_t)(m0 + row) * 256 + kc);
            sBr[i] = *(const float4*)(Bw + (size_t)(n0g + row) * 512 + k0 + kq * 4);
        }
    };
    auto store_tiles = [&](int buf) {
        uint32_t* sa = sh + buf * 2 * OPWRD;
        uint32_t* sb = sa + OPWRD;
        #pragma unroll
        for (int i = 0; i < 4; i++) {
            int row  = rbase + 32 * i;
            int base = kb * KBWRD + row * 8;
            sa[base + (((0 << 1) | par) ^ xr)] = f2tf32(sAr[i].x);
            sa[base + (((1 << 1) | par) ^ xr)] = f2tf32(sAr[i].y);
            sa[base + (((2 << 1) | par) ^ xr)] = f2tf32(sAr[i].z);
            sa[base + (((3 << 1) | par) ^ xr)] = f2tf32(sAr[i].w);
            sb[base + (((0 << 1) | par) ^ xr)] = f2tf32(sBr[i].x);
            sb[base + (((1 << 1) | par) ^ xr)] = f2tf32(sBr[i].y);
            sb[base + (((2 << 1) | par) ^ xr)] = f2tf32(sBr[i].z);
            sb[base + (((3 << 1) | par) ^ xr)] = f2tf32(sBr[i].w);
        }
    };
    auto compute = [&](int buf) {
        const uint32_t* sa = sh + buf * 2 * OPWRD;
        const uint32_t* sb = sa + OPWRD;
        #pragma unroll
        for (int kk = 0; kk < 4; kk++) {
            uint2 bf[4];
            #pragma unroll
            for (int nt = 0; nt < 4; nt++) {
                int n = wn * 32 + nt * 8 + r;
                bf[nt] = *(const uint2*)&sb[kk * KBWRD + n * 8 + cx];
            }
            uint2 alo[4], ahi[4];
            #pragma unroll
            for (int mt = 0; mt < 4; mt++) {
                int row = wm * 64 + mt * 16 + r;
                alo[mt] = *(const uint2*)&sa[kk * KBWRD + row * 8 + cx];
                ahi[mt] = *(const uint2*)&sa[kk * KBWRD + (row + 8) * 8 + cx];
            }
            #pragma unroll
            for (int mt = 0; mt < 4; mt++)
                #pragma unroll
                for (int nt = 0; nt < 4; nt++)
                    MMA_TF32(acc[mt][nt], alo[mt].x, ahi[mt].x,
                             alo[mt].y, ahi[mt].y, bf[nt].x, bf[nt].y);
        }
    };

    load_tiles(0);
    store_tiles(0);
    __syncthreads();
    #pragma unroll 1
    for (int kt = 0; kt < 16; kt++) {
        if (kt + 1 < 16) load_tiles(kt + 1);
        compute(kt & 1);
        if (kt + 1 < 16) store_tiles((kt + 1) & 1);
        __syncthreads();
    }

    const int c2 = (lane & 3) << 1;
    #pragma unroll
    for (int mt = 0; mt < 4; mt++) {
        int m = m0 + wm * 64 + mt * 16 + r;
        #pragma unroll
        for (int nt = 0; nt < 4; nt++) {
            int n = n0g + wn * 32 + nt * 8 + c2;
            float* a = acc[mt][nt];
            float b0 = bias[n], b1 = bias[n + 1];
            *(float2*)(out + (size_t)m * 256 + n)       = make_float2(a[0] + b0, a[1] + b1);
            *(float2*)(out + (size_t)(m + 8) * 256 + n) = make_float2(a[2] + b0, a[3] + b1);
        }
    }
}

// ---------------------------------------------------------------------------
// Spatial linear attention (attend over N=2048). Block = (bt, h), 8 warps.
// ---------------------------------------------------------------------------
#define SQS 36
__global__ __launch_bounds__(256)
void spatial_attn_kernel(const float* __restrict__ q, const float* __restrict__ k,
                         const float* __restrict__ v, float* __restrict__ o)
{
    __shared__ float s_part[8][32][SQS];
    __shared__ float s_kvs[32][SQS];
    __shared__ float s_ksp[8][32];
    __shared__ float s_kss[32];

    const int bt = blockIdx.x;
    const int h  = blockIdx.y;
    const int tid = threadIdx.x;
    const int w = tid >> 5, lane = tid & 31;

    const size_t baseBT = (size_t)bt * N_ * D_ + h * HD_;

    const int mg = lane >> 2;
    const int dg = lane & 3;
    float acc[4][8] = {};
    float kss[4] = {0.f, 0.f, 0.f, 0.f};

    const int l0w = w * 256;
    #pragma unroll 4
    for (int l = l0w; l < l0w + 256; l++) {
        const float* rk = k + baseBT + (size_t)l * D_;
        const float* rv = v + baseBT + (size_t)l * D_;
        float4 kf = *(const float4*)(rk + mg * 4);
        float4 va = *(const float4*)(rv + dg * 8);
        float4 vb = *(const float4*)(rv + dg * 8 + 4);
        float kk[4] = {kf.x, kf.y, kf.z, kf.w};
        float vv[8] = {va.x, va.y, va.z, va.w, vb.x, vb.y, vb.z, vb.w};
        #pragma unroll
        for (int i = 0; i < 4; i++) {
            kss[i] += kk[i];
            #pragma unroll
            for (int j = 0; j < 8; j++)
                acc[i][j] = fmaf(kk[i], vv[j], acc[i][j]);
        }
    }
    #pragma unroll
    for (int i = 0; i < 4; i++) {
        *(float4*)&s_part[w][mg*4+i][dg*8]     = make_float4(acc[i][0], acc[i][1], acc[i][2], acc[i][3]);
        *(float4*)&s_part[w][mg*4+i][dg*8 + 4] = make_float4(acc[i][4], acc[i][5], acc[i][6], acc[i][7]);
    }
    if (dg == 0) {
        #pragma unroll
        for (int i = 0; i < 4; i++) s_ksp[w][mg*4+i] = kss[i];
    }
    __syncthreads();

    {
        int m = tid >> 3, dd = (tid & 7) * 4;
        float4 s = make_float4(0.f, 0.f, 0.f, 0.f);
        #pragma unroll
        for (int wi = 0; wi < 8; wi++) {
            float4 p = *(const float4*)&s_part[wi][m][dd];
            s.x += p.x; s.y += p.y; s.z += p.z; s.w += p.w;
        }
        *(float4*)&s_kvs[m][dd] = s;
        if (tid < 32) {
            float s2 = 0.f;
            #pragma unroll
            for (int wi = 0; wi < 8; wi++) s2 += s_ksp[wi][tid];
            s_kss[tid] = s2;
        }
    }
    __syncthreads();

    float* qs = &s_part[w][0][0];
    const int lg = lane >> 3;
    const int d4 = (lane & 7) * 4;

    for (int c = 0; c < 8; c++) {
        const int l0 = l0w + c * 32;
        #pragma unroll
        for (int i2 = 0; i2 < 8; i2++) {
            int idx = lane + i2 * 32;
            int rr = idx >> 3, f = idx & 7;
            *(float4*)(qs + rr * SQS + f * 4) =
                *(const float4*)(q + baseBT + (size_t)(l0 + rr) * D_ + f * 4);
        }
        __syncwarp();

        float num[8][4] = {};
        float den[8] = {};
        #pragma unroll
        for (int m = 0; m < 32; m++) {
            float km = s_kss[m];
            float4 kr = *(const float4*)&s_kvs[m][d4];
            #pragma unroll
            for (int i = 0; i < 8; i++) {
                float qm = qs[(i * 4 + lg) * SQS + m];
                den[i] = fmaf(qm, km, den[i]);
                num[i][0] = fmaf(qm, kr.x, num[i][0]);
                num[i][1] = fmaf(qm, kr.y, num[i][1]);
                num[i][2] = fmaf(qm, kr.z, num[i][2]);
                num[i][3] = fmaf(qm, kr.w, num[i][3]);
            }
        }
        #pragma unroll
        for (int i = 0; i < 8; i++) {
            int l = l0 + i * 4 + lg;
            float4 vf = *(const float4*)(v + baseBT + (size_t)l * D_ + d4);
            float ddn = fmaxf(den[i] + (float)N_, 1e-5f);
            float inv = 1.f / ddn;
            float4 rr;
            rr.x = (num[i][0] + (float)N_ * vf.x) * inv;
            rr.y = (num[i][1] + (float)N_ * vf.y) * inv;
            rr.z = (num[i][2] + (float)N_ * vf.z) * inv;
            rr.w = (num[i][3] + (float)N_ * vf.w) * inv;
            *(float4*)(o + baseBT + (size_t)l * D_ + d4) = rr;
        }
        __syncwarp();
    }
}

// ---------------------------------------------------------------------------
// Temporal linear attention (attend over T=24). Block = (b, n), warp = head.
// ---------------------------------------------------------------------------
#define TSM_KVS (8*32*SQS)
#define TSM_Q   (8*24*SQS)
#define TSM_BYTES ((TSM_KVS + TSM_Q + 8*32) * 4)
__global__ __launch_bounds__(256)
void temporal_attn_kernel(const float* __restrict__ q, const float* __restrict__ k,
                          const float* __restrict__ v, float* __restrict__ o)
{
    extern __shared__ float sm[];
    const int bn = blockIdx.x;
    const int b = bn >> 11;
    const int n = bn & 2047;
    const int tid = threadIdx.x;
    const int h = tid >> 5, lane = tid & 31;

    float* kvs_h = sm + h * 32 * SQS;
    float* q_h   = sm + TSM_KVS + h * 24 * SQS;
    float* kss_h = sm + TSM_KVS + TSM_Q + h * 32;

    const size_t base = ((size_t)b * T_ * N_ + n) * D_ + h * HD_;
    const size_t sT = (size_t)N_ * D_;

    const int mg = lane >> 2;
    const int dg = lane & 3;
    float acc[4][8] = {};
    float kss[4] = {0.f, 0.f, 0.f, 0.f};

    #pragma unroll
    for (int t = 0; t < T_; t++) {
        const float* rk = k + base + (size_t)t * sT;
        const float* rv = v + base + (size_t)t * sT;
        float4 kf = *(const float4*)(rk + mg * 4);
        float4 va = *(const float4*)(rv + dg * 8);
        float4 vb = *(const float4*)(rv + dg * 8 + 4);
        float kk[4] = {kf.x, kf.y, kf.z, kf.w};
        float vv[8] = {va.x, va.y, va.z, va.w, vb.x, vb.y, vb.z, vb.w};
        #pragma unroll
        for (int i = 0; i < 4; i++) {
            kss[i] += kk[i];
            #pragma unroll
            for (int j = 0; j < 8; j++)
                acc[i][j] = fmaf(kk[i], vv[j], acc[i][j]);
        }
    }
    #pragma unroll
    for (int i = 0; i < 4; i++) {
        *(float4*)(kvs_h + (mg*4+i) * SQS + dg*8)     = make_float4(acc[i][0], acc[i][1], acc[i][2], acc[i][3]);
        *(float4*)(kvs_h + (mg*4+i) * SQS + dg*8 + 4) = make_float4(acc[i][4], acc[i][5], acc[i][6], acc[i][7]);
    }
    if (dg == 0) {
        #pragma unroll
        for (int i = 0; i < 4; i++) kss_h[mg*4+i] = kss[i];
    }
    #pragma unroll
    for (int i = 0; i < 6; i++) {
        int idx = lane + i * 32;
        int t = idx >> 3, f = idx & 7;
        *(float4*)(q_h + t * SQS + f * 4) =
            *(const float4*)(q + base + (size_t)t * sT + f * 4);
    }
    __syncwarp();

    const int tg = lane >> 3;
    const int d4 = (lane & 7) * 4;
    float num[6][4] = {};
    float den[6] = {};
    #pragma unroll
    for (int m = 0; m < 32; m++) {
        float km = kss_h[m];
        float4 kr = *(const float4*)(kvs_h + m * SQS + d4);
        #pragma unroll
        for (int i = 0; i < 6; i++) {
            float qm = q_h[(tg * 6 + i) * SQS + m];
            den[i] = fmaf(qm, km, den[i]);
            num[i][0] = fmaf(qm, kr.x, num[i][0]);
            num[i][1] = fmaf(qm, kr.y, num[i][1]);
            num[i][2] = fmaf(qm, kr.z, num[i][2]);
            num[i][3] = fmaf(qm, kr.w, num[i][3]);
        }
    }
    #pragma unroll
    for (int i = 0; i < 6; i++) {
        int t = tg * 6 + i;
        float4 vf = *(const float4*)(v + base + (size_t)t * sT + d4);
        float ddn = fmaxf(den[i] + (float)T_, 1e-5f);
        float inv = 1.f / ddn;
        float4 rr;
        rr.x = (num[i][0] + (float)T_ * vf.x) * inv;
        rr.y = (num[i][1] + (float)T_ * vf.y) * inv;
        rr.z = (num[i][2] + (float)T_ * vf.z) * inv;
        rr.w = (num[i][3] + (float)T_ * vf.w) * inv;
        *(float4*)(o + base + (size_t)t * sT + d4) = rr;
    }
}

// ---------------------------------------------------------------------------
extern "C" void kernel_launch(void* const* d_in, const int* in_sizes, int n_in,
                              void* d_out, int out_size)
{
    const float* x     = (const float*)d_in[0];
    const float* w_qkv = (const float*)d_in[1];
    const float* w_out = (const float*)d_in[2];
    const float* b_out = (const float*)d_in[3];
    float* out = (float*)d_out;

    float *q, *k, *v, *os, *ot;
    cudaGetSymbolAddress((void**)&q,  g_q);
    cudaGetSymbolAddress((void**)&k,  g_k);
    cudaGetSymbolAddress((void**)&v,  g_v);
    cudaGetSymbolAddress((void**)&os, g_os);
    cudaGetSymbolAddress((void**)&ot, g_ot);

    cudaFuncSetAttribute(gemm_qkv_kernel,
                         cudaFuncAttributeMaxDynamicSharedMemorySize, G1_SMEM);
    cudaFuncSetAttribute(gemm_out_kernel,
                         cudaFuncAttributeMaxDynamicSharedMemorySize, G2_SMEM);
    cudaFuncSetAttribute(temporal_attn_kernel,
                         cudaFuncAttributeMaxDynamicSharedMemorySize, TSM_BYTES);

    // 1) QKV projection (tf32 mma, A-resident) + fused q/k l2norm
    gemm_qkv_kernel<<<MTOK / 128, 256, G1_SMEM>>>(x, w_qkv, q, k, v);

    // 2) spatial attention
    {
        dim3 grid(B_ * T_, H_);
        spatial_attn_kernel<<<grid, 256>>>(q, k, v, os);
    }
    // 3) temporal attention
    temporal_attn_kernel<<<B_ * N_, 256, TSM_BYTES>>>(q, k, v, ot);

    // 4) output projection + bias (tf32 mma, dual-A concat)
    {
        dim3 grid(2, MTOK / 128);
        gemm_out_kernel<<<grid, 256, G2_SMEM>>>(os, ot, w_out, b_out, out);
    }
}

// round 6
// speedup vs baseline: 2.7617x; 1.1181x over previous
#include <cuda_runtime.h>
#include <cuda_fp16.h>
#include <math.h>
#include <stdint.h>

#define B_  4
#define T_  24
#define N_  2048
#define D_  256
#define H_  8
#define HD_ 32
#define MTOK (B_*T_*N_)           // 196608 tokens
#define ELEMS ((size_t)MTOK * D_) // 50,331,648

// Scratch (device globals; allocation-free per harness rules)
__device__ float g_q [ELEMS];
__device__ float g_k [ELEMS];
__device__ float g_v [ELEMS];
__device__ float g_os[ELEMS];
__device__ float g_ot[ELEMS];

// ---------------------------------------------------------------------------
// fp16 mma helpers (m16n8k16, f32 accumulate) + ldmatrix
// ---------------------------------------------------------------------------
__device__ __forceinline__ uint32_t smem_u32(const void* p) {
    uint32_t a;
    asm("{ .reg .u64 t; cvta.to.shared.u64 t, %1; cvt.u32.u64 %0, t; }"
        : "=r"(a) : "l"(p));
    return a;
}
__device__ __forceinline__ uint32_t f2h2(float a, float b) {
    __half2 h = __floats2half2_rn(a, b);
    return *(uint32_t*)&h;
}
__device__ __forceinline__ uint2 f4h(float4 v) {
    return make_uint2(f2h2(v.x, v.y), f2h2(v.z, v.w));
}
__device__ __forceinline__ void ldm_x4(uint32_t* r, uint32_t addr) {
    asm volatile("ldmatrix.sync.aligned.m8n8.x4.shared.b16 {%0,%1,%2,%3}, [%4];"
                 : "=r"(r[0]), "=r"(r[1]), "=r"(r[2]), "=r"(r[3]) : "r"(addr));
}
#define MMA_F16(d, a0, a1, a2, a3, b0, b1)                                    \
    asm volatile("mma.sync.aligned.m16n8k16.row.col.f32.f16.f16.f32 "         \
                 "{%0,%1,%2,%3}, {%4,%5,%6,%7}, {%8,%9}, {%0,%1,%2,%3};"      \
                 : "+f"(d[0]), "+f"(d[1]), "+f"(d[2]), "+f"(d[3])             \
                 : "r"(a0), "r"(a1), "r"(a2), "r"(a3), "r"(b0), "r"(b1))

// Row strides: 80B (chunk tiles) and 528B (resident A). Both ≡16 (mod 128):
// 8 consecutive ldmatrix rows hit 8 distinct 16B bank groups -> conflict-free.
#define CH_STRIDE 80
#define CH_BYTES  (128*CH_STRIDE)     // 10240 per [128 rows][32 halfs] tile
#define AR_STRIDE 528
#define AR_BYTES  (128*AR_STRIDE)     // 67584 resident A (128x256 halfs)

// ===========================================================================
// GEMM1 (A-resident, fp16): qkv[M,768] = x[M,256] * w_qkv[768,256]^T
// One CTA per 128 rows; 6 n-tiles x 8 k-chunks, B double-buffered.
// Fused q/k per-head L2 norm in per-n-tile epilogue.
// ===========================================================================
#define G1_SMEM (AR_BYTES + 2*CH_BYTES)   // 88064

__global__ __launch_bounds__(256, 2)
void gemm_qkv_kernel(const float* __restrict__ A, const float* __restrict__ Bw,
                     float* __restrict__ outq, float* __restrict__ outk,
                     float* __restrict__ outv)
{
    extern __shared__ __align__(16) char smem[];
    const uint32_t sbase = smem_u32(smem);
    const int tid  = threadIdx.x;
    const int lane = tid & 31;
    const int wid  = tid >> 5;
    const int wm   = wid & 1;                 // m offset wm*64
    const int wn   = wid >> 1;                // n offset wn*32
    const int m0   = blockIdx.x * 128;

    const int ar = tid >> 1;                  // loader row 0..127
    const int ac = tid & 1;                   // loader k-half

    const int fr = lane & 15;                 // ldmatrix row within 16
    const int fc = (lane >> 4) * 16;          // ldmatrix 16B column select
    const int r  = lane >> 2;
    const int c2 = (lane & 3) << 1;

    // ---- prologue: A (128x256 f32) -> resident fp16 smem, once ----
    #pragma unroll
    for (int j = 0; j < 8; j++) {
        const float* ap = A + (size_t)(m0 + ar) * 256 + (ac * 8 + j) * 16;
        uint2 h0 = f4h(*(const float4*)(ap + 0));
        uint2 h1 = f4h(*(const float4*)(ap + 4));
        uint2 h2 = f4h(*(const float4*)(ap + 8));
        uint2 h3 = f4h(*(const float4*)(ap + 12));
        char* dst = smem + ar * AR_STRIDE + (ac * 8 + j) * 32;
        *(uint4*)(dst)      = make_uint4(h0.x, h0.y, h1.x, h1.y);
        *(uint4*)(dst + 16) = make_uint4(h2.x, h2.y, h3.x, h3.y);
    }

    uint2 hb[4];
    auto ldgB = [&](int it) {
        const int nt = it >> 3, kt = it & 7;
        const float* bp = Bw + (size_t)(nt * 128 + ar) * 256 + kt * 32 + ac * 16;
        hb[0] = f4h(*(const float4*)(bp + 0));
        hb[1] = f4h(*(const float4*)(bp + 4));
        hb[2] = f4h(*(const float4*)(bp + 8));
        hb[3] = f4h(*(const float4*)(bp + 12));
    };
    auto stsB = [&](int buf) {
        char* dst = smem + AR_BYTES + buf * CH_BYTES + ar * CH_STRIDE + ac * 32;
        *(uint4*)(dst)      = make_uint4(hb[0].x, hb[0].y, hb[1].x, hb[1].y);
        *(uint4*)(dst + 16) = make_uint4(hb[2].x, hb[2].y, hb[3].x, hb[3].y);
    };

    float acc[4][4][4];
    #pragma unroll
    for (int i = 0; i < 4; i++)
        #pragma unroll
        for (int j = 0; j < 4; j++)
            #pragma unroll
            for (int c = 0; c < 4; c++) acc[i][j][c] = 0.f;

    ldgB(0);
    stsB(0);
    __syncthreads();

    #pragma unroll 1
    for (int it = 0; it < 48; it++) {
        if (it + 1 < 48) ldgB(it + 1);

        // ---- compute: resident-A chunk (it&7) x B buffer (it&1) ----
        {
            const int kt = it & 7;
            const uint32_t abase = sbase + kt * 64;
            const uint32_t bbase = sbase + AR_BYTES + (it & 1) * CH_BYTES;
            #pragma unroll
            for (int s = 0; s < 2; s++) {
                uint32_t af[4][4], bf[2][4];
                #pragma unroll
                for (int mt = 0; mt < 4; mt++) {
                    int row = wm * 64 + mt * 16 + fr;
                    ldm_x4(af[mt], abase + row * AR_STRIDE + s * 32 + fc);
                }
                #pragma unroll
                for (int bi = 0; bi < 2; bi++) {
                    int row = wn * 32 + bi * 16 + fr;
                    ldm_x4(bf[bi], bbase + row * CH_STRIDE + s * 32 + fc);
                }
                #pragma unroll
                for (int mt = 0; mt < 4; mt++)
                    #pragma unroll
                    for (int nt2 = 0; nt2 < 4; nt2++) {
                        int bi = nt2 >> 1, od = nt2 & 1;
                        MMA_F16(acc[mt][nt2],
                                af[mt][0], af[mt][1], af[mt][2], af[mt][3],
                                bf[bi][od], bf[bi][od + 2]);
                    }
            }
        }

        // ---- per-n-tile epilogue ----
        if ((it & 7) == 7) {
            const int n0g = (it >> 3) * 128;
            const int sel = n0g >> 8;

            if (sel < 2) {   // q or k: fused per-head L2 norm
                #pragma unroll
                for (int mt = 0; mt < 4; mt++) {
                    float sslo = 0.f, sshi = 0.f;
                    #pragma unroll
                    for (int nt2 = 0; nt2 < 4; nt2++) {
                        sslo = fmaf(acc[mt][nt2][0], acc[mt][nt2][0], sslo);
                        sslo = fmaf(acc[mt][nt2][1], acc[mt][nt2][1], sslo);
                        sshi = fmaf(acc[mt][nt2][2], acc[mt][nt2][2], sshi);
                        sshi = fmaf(acc[mt][nt2][3], acc[mt][nt2][3], sshi);
                    }
                    sslo += __shfl_xor_sync(0xffffffffu, sslo, 1);
                    sslo += __shfl_xor_sync(0xffffffffu, sslo, 2);
                    sshi += __shfl_xor_sync(0xffffffffu, sshi, 1);
                    sshi += __shfl_xor_sync(0xffffffffu, sshi, 2);
                    float slo = 1.f / fmaxf(sqrtf(sslo), 1e-12f);
                    float shi = 1.f / fmaxf(sqrtf(sshi), 1e-12f);
                    #pragma unroll
                    for (int nt2 = 0; nt2 < 4; nt2++) {
                        acc[mt][nt2][0] *= slo; acc[mt][nt2][1] *= slo;
                        acc[mt][nt2][2] *= shi; acc[mt][nt2][3] *= shi;
                    }
                }
            }

            float* dst = (sel == 0) ? outq : ((sel == 1) ? outk : outv);
            #pragma unroll
            for (int mt = 0; mt < 4; mt++) {
                int m = m0 + wm * 64 + mt * 16 + r;
                #pragma unroll
                for (int nt2 = 0; nt2 < 4; nt2++) {
                    int col = ((n0g + wn * 32 + nt2 * 8 + c2) & 255);
                    float* a = acc[mt][nt2];
                    *(float2*)(dst + (size_t)m * 256 + col)       = make_float2(a[0], a[1]);
                    *(float2*)(dst + (size_t)(m + 8) * 256 + col) = make_float2(a[2], a[3]);
                    a[0] = a[1] = a[2] = a[3] = 0.f;
                }
            }
        }

        if (it + 1 < 48) stsB((it + 1) & 1);
        __syncthreads();
    }
}

// ===========================================================================
// GEMM2 (fp16): out[M,256] = [os|ot][M,512] * w_out[256,512]^T + b
// 128x128 tile, K=512 in 16 chunks of 32, A+B double buffered.
// ===========================================================================
#define G2_SMEM (4*CH_BYTES)   // 40960

__global__ __launch_bounds__(256, 2)
void gemm_out_kernel(const float* __restrict__ A0, const float* __restrict__ A1,
                     const float* __restrict__ Bw,
                     const float* __restrict__ bias,
                     float* __restrict__ out)
{
    extern __shared__ __align__(16) char smem[];
    const uint32_t sbase = smem_u32(smem);
    const int tid  = threadIdx.x;
    const int lane = tid & 31;
    const int wid  = tid >> 5;
    const int wm   = wid & 1;
    const int wn   = wid >> 1;
    const int m0   = blockIdx.y * 128;
    const int n0g  = blockIdx.x * 128;

    const int ar = tid >> 1;
    const int ac = tid & 1;
    const int fr = lane & 15;
    const int fc = (lane >> 4) * 16;
    const int r  = lane >> 2;
    const int c2 = (lane & 3) << 1;

    uint2 ha[4], hb[4];
    auto ldg = [&](int kt) {
        const int k0 = kt * 32;
        const float* Asrc = (k0 < 256) ? A0 : A1;
        const int kc = k0 & 255;
        const float* apx = Asrc + (size_t)(m0 + ar) * 256 + kc + ac * 16;
        ha[0] = f4h(*(const float4*)(apx + 0));
        ha[1] = f4h(*(const float4*)(apx + 4));
        ha[2] = f4h(*(const float4*)(apx + 8));
        ha[3] = f4h(*(const float4*)(apx + 12));
        const float* bp = Bw + (size_t)(n0g + ar) * 512 + k0 + ac * 16;
        hb[0] = f4h(*(const float4*)(bp + 0));
        hb[1] = f4h(*(const float4*)(bp + 4));
        hb[2] = f4h(*(const float4*)(bp + 8));
        hb[3] = f4h(*(const float4*)(bp + 12));
    };
    auto sts = [&](int buf) {
        char* da = smem + buf * 2 * CH_BYTES + ar * CH_STRIDE + ac * 32;
        *(uint4*)(da)      = make_uint4(ha[0].x, ha[0].y, ha[1].x, ha[1].y);
        *(uint4*)(da + 16) = make_uint4(ha[2].x, ha[2].y, ha[3].x, ha[3].y);
        char* db = da + CH_BYTES;
        *(uint4*)(db)      = make_uint4(hb[0].x, hb[0].y, hb[1].x, hb[1].y);
        *(uint4*)(db + 16) = make_uint4(hb[2].x, hb[2].y, hb[3].x, hb[3].y);
    };

    float acc[4][4][4];
    #pragma unroll
    for (int i = 0; i < 4; i++)
        #pragma unroll
        for (int j = 0; j < 4; j++)
            #pragma unroll
            for (int c = 0; c < 4; c++) acc[i][j][c] = 0.f;

    ldg(0);
    sts(0);
    __syncthreads();

    #pragma unroll 1
    for (int kt = 0; kt < 16; kt++) {
        if (kt + 1 < 16) ldg(kt + 1);

        {
            const uint32_t abase = sbase + (kt & 1) * 2 * CH_BYTES;
            const uint32_t bbase = abase + CH_BYTES;
            #pragma unroll
            for (int s = 0; s < 2; s++) {
                uint32_t af[4][4], bf[2][4];
                #pragma unroll
                for (int mt = 0; mt < 4; mt++) {
                    int row = wm * 64 + mt * 16 + fr;
                    ldm_x4(af[mt], abase + row * CH_STRIDE + s * 32 + fc);
                }
                #pragma unroll
                for (int bi = 0; bi < 2; bi++) {
                    int row = wn * 32 + bi * 16 + fr;
                    ldm_x4(bf[bi], bbase + row * CH_STRIDE + s * 32 + fc);
                }
                #pragma unroll
                for (int mt = 0; mt < 4; mt++)
                    #pragma unroll
                    for (int nt2 = 0; nt2 < 4; nt2++) {
                        int bi = nt2 >> 1, od = nt2 & 1;
                        MMA_F16(acc[mt][nt2],
                                af[mt][0], af[mt][1], af[mt][2], af[mt][3],
                                bf[bi][od], bf[bi][od + 2]);
                    }
            }
        }

        if (kt + 1 < 16) sts((kt + 1) & 1);
        __syncthreads();
    }

    #pragma unroll
    for (int mt = 0; mt < 4; mt++) {
        int m = m0 + wm * 64 + mt * 16 + r;
        #pragma unroll
        for (int nt = 0; nt < 4; nt++) {
            int n = n0g + wn * 32 + nt * 8 + c2;
            float* a = acc[mt][nt];
            float b0 = bias[n], b1 = bias[n + 1];
            *(float2*)(out + (size_t)m * 256 + n)       = make_float2(a[0] + b0, a[1] + b1);
            *(float2*)(out + (size_t)(m + 8) * 256 + n) = make_float2(a[2] + b0, a[3] + b1);
        }
    }
}

// ---------------------------------------------------------------------------
// Spatial linear attention (attend over N=2048). Block = (bt, h), 8 warps.
// ---------------------------------------------------------------------------
#define SQS 36
__global__ __launch_bounds__(256)
void spatial_attn_kernel(const float* __restrict__ q, const float* __restrict__ k,
                         const float* __restrict__ v, float* __restrict__ o)
{
    __shared__ float s_part[8][32][SQS];
    __shared__ float s_kvs[32][SQS];
    __shared__ float s_ksp[8][32];
    __shared__ float s_kss[32];

    const int bt = blockIdx.x;
    const int h  = blockIdx.y;
    const int tid = threadIdx.x;
    const int w = tid >> 5, lane = tid & 31;

    const size_t baseBT = (size_t)bt * N_ * D_ + h * HD_;

    const int mg = lane >> 2;
    const int dg = lane & 3;
    float acc[4][8] = {};
    float kss[4] = {0.f, 0.f, 0.f, 0.f};

    const int l0w = w * 256;
    #pragma unroll 4
    for (int l = l0w; l < l0w + 256; l++) {
        const float* rk = k + baseBT + (size_t)l * D_;
        const float* rv = v + baseBT + (size_t)l * D_;
        float4 kf = *(const float4*)(rk + mg * 4);
        float4 va = *(const float4*)(rv + dg * 8);
        float4 vb = *(const float4*)(rv + dg * 8 + 4);
        float kk[4] = {kf.x, kf.y, kf.z, kf.w};
        float vv[8] = {va.x, va.y, va.z, va.w, vb.x, vb.y, vb.z, vb.w};
        #pragma unroll
        for (int i = 0; i < 4; i++) {
            kss[i] += kk[i];
            #pragma unroll
            for (int j = 0; j < 8; j++)
                acc[i][j] = fmaf(kk[i], vv[j], acc[i][j]);
        }
    }
    #pragma unroll
    for (int i = 0; i < 4; i++) {
        *(float4*)&s_part[w][mg*4+i][dg*8]     = make_float4(acc[i][0], acc[i][1], acc[i][2], acc[i][3]);
        *(float4*)&s_part[w][mg*4+i][dg*8 + 4] = make_float4(acc[i][4], acc[i][5], acc[i][6], acc[i][7]);
    }
    if (dg == 0) {
        #pragma unroll
        for (int i = 0; i < 4; i++) s_ksp[w][mg*4+i] = kss[i];
    }
    __syncthreads();

    {
        int m = tid >> 3, dd = (tid & 7) * 4;
        float4 s = make_float4(0.f, 0.f, 0.f, 0.f);
        #pragma unroll
        for (int wi = 0; wi < 8; wi++) {
            float4 p = *(const float4*)&s_part[wi][m][dd];
            s.x += p.x; s.y += p.y; s.z += p.z; s.w += p.w;
        }
        *(float4*)&s_kvs[m][dd] = s;
        if (tid < 32) {
            float s2 = 0.f;
            #pragma unroll
            for (int wi = 0; wi < 8; wi++) s2 += s_ksp[wi][tid];
            s_kss[tid] = s2;
        }
    }
    __syncthreads();

    float* qs = &s_part[w][0][0];
    const int lg = lane >> 3;
    const int d4 = (lane & 7) * 4;

    for (int c = 0; c < 8; c++) {
        const int l0 = l0w + c * 32;
        #pragma unroll
        for (int i2 = 0; i2 < 8; i2++) {
            int idx = lane + i2 * 32;
            int rr = idx >> 3, f = idx & 7;
            *(float4*)(qs + rr * SQS + f * 4) =
                *(const float4*)(q + baseBT + (size_t)(l0 + rr) * D_ + f * 4);
        }
        __syncwarp();

        float num[8][4] = {};
        float den[8] = {};
        #pragma unroll
        for (int m = 0; m < 32; m++) {
            float km = s_kss[m];
            float4 kr = *(const float4*)&s_kvs[m][d4];
            #pragma unroll
            for (int i = 0; i < 8; i++) {
                float qm = qs[(i * 4 + lg) * SQS + m];
                den[i] = fmaf(qm, km, den[i]);
                num[i][0] = fmaf(qm, kr.x, num[i][0]);
                num[i][1] = fmaf(qm, kr.y, num[i][1]);
                num[i][2] = fmaf(qm, kr.z, num[i][2]);
                num[i][3] = fmaf(qm, kr.w, num[i][3]);
            }
        }
        #pragma unroll
        for (int i = 0; i < 8; i++) {
            int l = l0 + i * 4 + lg;
            float4 vf = *(const float4*)(v + baseBT + (size_t)l * D_ + d4);
            float ddn = fmaxf(den[i] + (float)N_, 1e-5f);
            float inv = 1.f / ddn;
            float4 rr;
            rr.x = (num[i][0] + (float)N_ * vf.x) * inv;
            rr.y = (num[i][1] + (float)N_ * vf.y) * inv;
            rr.z = (num[i][2] + (float)N_ * vf.z) * inv;
            rr.w = (num[i][3] + (float)N_ * vf.w) * inv;
            *(float4*)(o + baseBT + (size_t)l * D_ + d4) = rr;
        }
        __syncwarp();
    }
}

// ---------------------------------------------------------------------------
// Temporal linear attention (attend over T=24). Block = (b, n), warp = head.
// ---------------------------------------------------------------------------
#define TSM_KVS (8*32*SQS)
#define TSM_Q   (8*24*SQS)
#define TSM_BYTES ((TSM_KVS + TSM_Q + 8*32) * 4)
__global__ __launch_bounds__(256)
void temporal_attn_kernel(const float* __restrict__ q, const float* __restrict__ k,
                          const float* __restrict__ v, float* __restrict__ o)
{
    extern __shared__ float sm[];
    const int bn = blockIdx.x;
    const int b = bn >> 11;
    const int n = bn & 2047;
    const int tid = threadIdx.x;
    const int h = tid >> 5, lane = tid & 31;

    float* kvs_h = sm + h * 32 * SQS;
    float* q_h   = sm + TSM_KVS + h * 24 * SQS;
    float* kss_h = sm + TSM_KVS + TSM_Q + h * 32;

    const size_t base = ((size_t)b * T_ * N_ + n) * D_ + h * HD_;
    const size_t sT = (size_t)N_ * D_;

    const int mg = lane >> 2;
    const int dg = lane & 3;
    float acc[4][8] = {};
    float kss[4] = {0.f, 0.f, 0.f, 0.f};

    #pragma unroll
    for (int t = 0; t < T_; t++) {
        const float* rk = k + base + (size_t)t * sT;
        const float* rv = v + base + (size_t)t * sT;
        float4 kf = *(const float4*)(rk + mg * 4);
        float4 va = *(const float4*)(rv + dg * 8);
        float4 vb = *(const float4*)(rv + dg * 8 + 4);
        float kk[4] = {kf.x, kf.y, kf.z, kf.w};
        float vv[8] = {va.x, va.y, va.z, va.w, vb.x, vb.y, vb.z, vb.w};
        #pragma unroll
        for (int i = 0; i < 4; i++) {
            kss[i] += kk[i];
            #pragma unroll
            for (int j = 0; j < 8; j++)
                acc[i][j] = fmaf(kk[i], vv[j], acc[i][j]);
        }
    }
    #pragma unroll
    for (int i = 0; i < 4; i++) {
        *(float4*)(kvs_h + (mg*4+i) * SQS + dg*8)     = make_float4(acc[i][0], acc[i][1], acc[i][2], acc[i][3]);
        *(float4*)(kvs_h + (mg*4+i) * SQS + dg*8 + 4) = make_float4(acc[i][4], acc[i][5], acc[i][6], acc[i][7]);
    }
    if (dg == 0) {
        #pragma unroll
        for (int i = 0; i < 4; i++) kss_h[mg*4+i] = kss[i];
    }
    #pragma unroll
    for (int i = 0; i < 6; i++) {
        int idx = lane + i * 32;
        int t = idx >> 3, f = idx & 7;
        *(float4*)(q_h + t * SQS + f * 4) =
            *(const float4*)(q + base + (size_t)t * sT + f * 4);
    }
    __syncwarp();

    const int tg = lane >> 3;
    const int d4 = (lane & 7) * 4;
    float num[6][4] = {};
    float den[6] = {};
    #pragma unroll
    for (int m = 0; m < 32; m++) {
        float km = kss_h[m];
        float4 kr = *(const float4*)(kvs_h + m * SQS + d4);
        #pragma unroll
        for (int i = 0; i < 6; i++) {
            float qm = q_h[(tg * 6 + i) * SQS + m];
            den[i] = fmaf(qm, km, den[i]);
            num[i][0] = fmaf(qm, kr.x, num[i][0]);
            num[i][1] = fmaf(qm, kr.y, num[i][1]);
            num[i][2] = fmaf(qm, kr.z, num[i][2]);
            num[i][3] = fmaf(qm, kr.w, num[i][3]);
        }
    }
    #pragma unroll
    for (int i = 0; i < 6; i++) {
        int t = tg * 6 + i;
        float4 vf = *(const float4*)(v + base + (size_t)t * sT + d4);
        float ddn = fmaxf(den[i] + (float)T_, 1e-5f);
        float inv = 1.f / ddn;
        float4 rr;
        rr.x = (num[i][0] + (float)T_ * vf.x) * inv;
        rr.y = (num[i][1] + (float)T_ * vf.y) * inv;
        rr.z = (num[i][2] + (float)T_ * vf.z) * inv;
        rr.w = (num[i][3] + (float)T_ * vf.w) * inv;
        *(float4*)(o + base + (size_t)t * sT + d4) = rr;
    }
}

// ---------------------------------------------------------------------------
extern "C" void kernel_launch(void* const* d_in, const int* in_sizes, int n_in,
                              void* d_out, int out_size)
{
    const float* x     = (const float*)d_in[0];
    const float* w_qkv = (const float*)d_in[1];
    const float* w_out = (const float*)d_in[2];
    const float* b_out = (const float*)d_in[3];
    float* out = (float*)d_out;

    float *q, *k, *v, *os, *ot;
    cudaGetSymbolAddress((void**)&q,  g_q);
    cudaGetSymbolAddress((void**)&k,  g_k);
    cudaGetSymbolAddress((void**)&v,  g_v);
    cudaGetSymbolAddress((void**)&os, g_os);
    cudaGetSymbolAddress((void**)&ot, g_ot);

    cudaFuncSetAttribute(gemm_qkv_kernel,
                         cudaFuncAttributeMaxDynamicSharedMemorySize, G1_SMEM);
    cudaFuncSetAttribute(gemm_out_kernel,
                         cudaFuncAttributeMaxDynamicSharedMemorySize, G2_SMEM);
    cudaFuncSetAttribute(temporal_attn_kernel,
                         cudaFuncAttributeMaxDynamicSharedMemorySize, TSM_BYTES);

    // 1) QKV projection (fp16 mma, A-resident) + fused q/k l2norm
    gemm_qkv_kernel<<<MTOK / 128, 256, G1_SMEM>>>(x, w_qkv, q, k, v);

    // 2) spatial attention
    {
        dim3 grid(B_ * T_, H_);
        spatial_attn_kernel<<<grid, 256>>>(q, k, v, os);
    }
    // 3) temporal attention
    temporal_attn_kernel<<<B_ * N_, 256, TSM_BYTES>>>(q, k, v, ot);

    // 4) output projection + bias (fp16 mma, dual-A concat)
    {
        dim3 grid(2, MTOK / 128);
        gemm_out_kernel<<<grid, 256, G2_SMEM>>>(os, ot, w_out, b_out, out);
    }
}

// round 7
// speedup vs baseline: 3.4813x; 1.2605x over previous
#include <cuda_runtime.h>
#include <cuda_fp16.h>
#include <math.h>
#include <stdint.h>

#define B_  4
#define T_  24
#define N_  2048
#define D_  256
#define H_  8
#define HD_ 32
#define MTOK (B_*T_*N_)           // 196608 tokens
#define ELEMS ((size_t)MTOK * D_) // 50,331,648

// Scratch (device globals; allocation-free per harness rules). All fp16.
__device__ __half g_q [ELEMS];
__device__ __half g_k [ELEMS];
__device__ __half g_v [ELEMS];
__device__ __half g_os[ELEMS];
__device__ __half g_ot[ELEMS];
__device__ __half g_wqh[768*256];
__device__ __half g_woh[256*512];

// ---------------------------------------------------------------------------
// helpers
// ---------------------------------------------------------------------------
__device__ __forceinline__ uint32_t smem_u32(const void* p) {
    uint32_t a;
    asm("{ .reg .u64 t; cvta.to.shared.u64 t, %1; cvt.u32.u64 %0, t; }"
        : "=r"(a) : "l"(p));
    return a;
}
__device__ __forceinline__ uint32_t f2h2(float a, float b) {
    __half2 h = __floats2half2_rn(a, b);
    return *(uint32_t*)&h;
}
__device__ __forceinline__ uint2 f4h(float4 v) {
    return make_uint2(f2h2(v.x, v.y), f2h2(v.z, v.w));
}
__device__ __forceinline__ float2 h2f2(uint32_t h) {
    return __half22float2(*(__half2*)&h);
}
__device__ __forceinline__ void ldm_x4(uint32_t* r, uint32_t addr) {
    asm volatile("ldmatrix.sync.aligned.m8n8.x4.shared.b16 {%0,%1,%2,%3}, [%4];"
                 : "=r"(r[0]), "=r"(r[1]), "=r"(r[2]), "=r"(r[3]) : "r"(addr));
}
#define MMA_F16(d, a0, a1, a2, a3, b0, b1)                                    \
    asm volatile("mma.sync.aligned.m16n8k16.row.col.f32.f16.f16.f32 "         \
                 "{%0,%1,%2,%3}, {%4,%5,%6,%7}, {%8,%9}, {%0,%1,%2,%3};"      \
                 : "+f"(d[0]), "+f"(d[1]), "+f"(d[2]), "+f"(d[3])             \
                 : "r"(a0), "r"(a1), "r"(a2), "r"(a3), "r"(b0), "r"(b1))

// Row strides: 80B (chunk tiles) and 528B (resident A). Both ≡16 (mod 128).
#define CH_STRIDE 80
#define CH_BYTES  (128*CH_STRIDE)
#define AR_STRIDE 528
#define AR_BYTES  (128*AR_STRIDE)

// ---------------------------------------------------------------------------
// weight pre-conversion: f32 -> f16 (once per launch, ~330K elems)
// ---------------------------------------------------------------------------
__global__ void cvt_weights_kernel(const float* __restrict__ wq,
                                   const float* __restrict__ wo,
                                   __half* __restrict__ wqh,
                                   __half* __restrict__ woh)
{
    int i = blockIdx.x * blockDim.x + threadIdx.x;
    const int NQ = 768 * 256 / 2;
    const int NO = 256 * 512 / 2;
    if (i < NQ) {
        float2 f = *(const float2*)(wq + i * 2);
        *(uint32_t*)(wqh + i * 2) = f2h2(f.x, f.y);
    } else if (i < NQ + NO) {
        int j = i - NQ;
        float2 f = *(const float2*)(wo + j * 2);
        *(uint32_t*)(woh + j * 2) = f2h2(f.x, f.y);
    }
}

// ===========================================================================
// GEMM1 (A-resident, fp16): qkv[M,768] = x[M,256] * w_qkv[768,256]^T
// A converted f32->f16 once into resident smem; B (half) double-buffered.
// Fused q/k per-head L2 norm; outputs stored as half.
// ===========================================================================
#define G1_SMEM (AR_BYTES + 2*CH_BYTES)   // 88064

__global__ __launch_bounds__(256, 2)
void gemm_qkv_kernel(const float* __restrict__ A, const __half* __restrict__ Bw,
                     __half* __restrict__ outq, __half* __restrict__ outk,
                     __half* __restrict__ outv)
{
    extern __shared__ __align__(16) char smem[];
    const uint32_t sbase = smem_u32(smem);
    const int tid  = threadIdx.x;
    const int lane = tid & 31;
    const int wid  = tid >> 5;
    const int wm   = wid & 1;
    const int wn   = wid >> 1;
    const int m0   = blockIdx.x * 128;

    const int ar = tid >> 1;
    const int ac = tid & 1;
    const int fr = lane & 15;
    const int fc = (lane >> 4) * 16;
    const int r  = lane >> 2;
    const int c2 = (lane & 3) << 1;

    // ---- prologue: A (128x256 f32) -> resident fp16 smem, once ----
    #pragma unroll
    for (int j = 0; j < 8; j++) {
        const float* ap = A + (size_t)(m0 + ar) * 256 + (ac * 8 + j) * 16;
        uint2 h0 = f4h(*(const float4*)(ap + 0));
        uint2 h1 = f4h(*(const float4*)(ap + 4));
        uint2 h2 = f4h(*(const float4*)(ap + 8));
        uint2 h3 = f4h(*(const float4*)(ap + 12));
        char* dst = smem + ar * AR_STRIDE + (ac * 8 + j) * 32;
        *(uint4*)(dst)      = make_uint4(h0.x, h0.y, h1.x, h1.y);
        *(uint4*)(dst + 16) = make_uint4(h2.x, h2.y, h3.x, h3.y);
    }

    uint4 hb0, hb1;
    auto ldgB = [&](int it) {
        const int nt = it >> 3, kt = it & 7;
        const __half* bp = Bw + (size_t)(nt * 128 + ar) * 256 + kt * 32 + ac * 16;
        hb0 = *(const uint4*)(bp);
        hb1 = *(const uint4*)(bp + 8);
    };
    auto stsB = [&](int buf) {
        char* dst = smem + AR_BYTES + buf * CH_BYTES + ar * CH_STRIDE + ac * 32;
        *(uint4*)(dst)      = hb0;
        *(uint4*)(dst + 16) = hb1;
    };

    float acc[4][4][4];
    #pragma unroll
    for (int i = 0; i < 4; i++)
        #pragma unroll
        for (int j = 0; j < 4; j++)
            #pragma unroll
            for (int c = 0; c < 4; c++) acc[i][j][c] = 0.f;

    ldgB(0);
    stsB(0);
    __syncthreads();

    #pragma unroll 1
    for (int it = 0; it < 48; it++) {
        if (it + 1 < 48) ldgB(it + 1);

        {
            const int kt = it & 7;
            const uint32_t abase = sbase + kt * 64;
            const uint32_t bbase = sbase + AR_BYTES + (it & 1) * CH_BYTES;
            #pragma unroll
            for (int s = 0; s < 2; s++) {
                uint32_t af[4][4], bf[2][4];
                #pragma unroll
                for (int mt = 0; mt < 4; mt++) {
                    int row = wm * 64 + mt * 16 + fr;
                    ldm_x4(af[mt], abase + row * AR_STRIDE + s * 32 + fc);
                }
                #pragma unroll
                for (int bi = 0; bi < 2; bi++) {
                    int row = wn * 32 + bi * 16 + fr;
                    ldm_x4(bf[bi], bbase + row * CH_STRIDE + s * 32 + fc);
                }
                #pragma unroll
                for (int mt = 0; mt < 4; mt++)
                    #pragma unroll
                    for (int nt2 = 0; nt2 < 4; nt2++) {
                        int bi = nt2 >> 1, od = nt2 & 1;
                        MMA_F16(acc[mt][nt2],
                                af[mt][0], af[mt][1], af[mt][2], af[mt][3],
                                bf[bi][od], bf[bi][od + 2]);
                    }
            }
        }

        if ((it & 7) == 7) {
            const int n0g = (it >> 3) * 128;
            const int sel = n0g >> 8;

            if (sel < 2) {
                #pragma unroll
                for (int mt = 0; mt < 4; mt++) {
                    float sslo = 0.f, sshi = 0.f;
                    #pragma unroll
                    for (int nt2 = 0; nt2 < 4; nt2++) {
                        sslo = fmaf(acc[mt][nt2][0], acc[mt][nt2][0], sslo);
                        sslo = fmaf(acc[mt][nt2][1], acc[mt][nt2][1], sslo);
                        sshi = fmaf(acc[mt][nt2][2], acc[mt][nt2][2], sshi);
                        sshi = fmaf(acc[mt][nt2][3], acc[mt][nt2][3], sshi);
                    }
                    sslo += __shfl_xor_sync(0xffffffffu, sslo, 1);
                    sslo += __shfl_xor_sync(0xffffffffu, sslo, 2);
                    sshi += __shfl_xor_sync(0xffffffffu, sshi, 1);
                    sshi += __shfl_xor_sync(0xffffffffu, sshi, 2);
                    float slo = 1.f / fmaxf(sqrtf(sslo), 1e-12f);
                    float shi = 1.f / fmaxf(sqrtf(sshi), 1e-12f);
                    #pragma unroll
                    for (int nt2 = 0; nt2 < 4; nt2++) {
                        acc[mt][nt2][0] *= slo; acc[mt][nt2][1] *= slo;
                        acc[mt][nt2][2] *= shi; acc[mt][nt2][3] *= shi;
                    }
                }
            }

            __half* dst = (sel == 0) ? outq : ((sel == 1) ? outk : outv);
            #pragma unroll
            for (int mt = 0; mt < 4; mt++) {
                int m = m0 + wm * 64 + mt * 16 + r;
                #pragma unroll
                for (int nt2 = 0; nt2 < 4; nt2++) {
                    int col = ((n0g + wn * 32 + nt2 * 8 + c2) & 255);
                    float* a = acc[mt][nt2];
                    *(uint32_t*)(dst + (size_t)m * 256 + col)       = f2h2(a[0], a[1]);
                    *(uint32_t*)(dst + (size_t)(m + 8) * 256 + col) = f2h2(a[2], a[3]);
                    a[0] = a[1] = a[2] = a[3] = 0.f;
                }
            }
        }

        if (it + 1 < 48) stsB((it + 1) & 1);
        __syncthreads();
    }
}

// ===========================================================================
// GEMM2 (fp16 in/out f32): out[M,256] = [os|ot][M,512] * w_out[256,512]^T + b
// All operands already fp16 -> loaders are pure copies (no cvt).
// ===========================================================================
#define G2_SMEM (4*CH_BYTES)   // 40960

__global__ __launch_bounds__(256, 2)
void gemm_out_kernel(const __half* __restrict__ A0, const __half* __restrict__ A1,
                     const __half* __restrict__ Bw,
                     const float* __restrict__ bias,
                     float* __restrict__ out)
{
    extern __shared__ __align__(16) char smem[];
    const uint32_t sbase = smem_u32(smem);
    const int tid  = threadIdx.x;
    const int lane = tid & 31;
    const int wid  = tid >> 5;
    const int wm   = wid & 1;
    const int wn   = wid >> 1;
    const int m0   = blockIdx.y * 128;
    const int n0g  = blockIdx.x * 128;

    const int ar = tid >> 1;
    const int ac = tid & 1;
    const int fr = lane & 15;
    const int fc = (lane >> 4) * 16;
    const int r  = lane >> 2;
    const int c2 = (lane & 3) << 1;

    uint4 ua0, ua1, ub0, ub1;
    auto ldg = [&](int kt) {
        const int k0 = kt * 32;
        const __half* Asrc = (k0 < 256) ? A0 : A1;
        const int kc = k0 & 255;
        const __half* ap = Asrc + (size_t)(m0 + ar) * 256 + kc + ac * 16;
        ua0 = *(const uint4*)(ap);
        ua1 = *(const uint4*)(ap + 8);
        const __half* bp = Bw + (size_t)(n0g + ar) * 512 + k0 + ac * 16;
        ub0 = *(const uint4*)(bp);
        ub1 = *(const uint4*)(bp + 8);
    };
    auto sts = [&](int buf) {
        char* da = smem + buf * 2 * CH_BYTES + ar * CH_STRIDE + ac * 32;
        *(uint4*)(da)      = ua0;
        *(uint4*)(da + 16) = ua1;
        char* db = da + CH_BYTES;
        *(uint4*)(db)      = ub0;
        *(uint4*)(db + 16) = ub1;
    };

    float acc[4][4][4];
    #pragma unroll
    for (int i = 0; i < 4; i++)
        #pragma unroll
        for (int j = 0; j < 4; j++)
            #pragma unroll
            for (int c = 0; c < 4; c++) acc[i][j][c] = 0.f;

    ldg(0);
    sts(0);
    __syncthreads();

    #pragma unroll 1
    for (int kt = 0; kt < 16; kt++) {
        if (kt + 1 < 16) ldg(kt + 1);

        {
            const uint32_t abase = sbase + (kt & 1) * 2 * CH_BYTES;
            const uint32_t bbase = abase + CH_BYTES;
            #pragma unroll
            for (int s = 0; s < 2; s++) {
                uint32_t af[4][4], bf[2][4];
                #pragma unroll
                for (int mt = 0; mt < 4; mt++) {
                    int row = wm * 64 + mt * 16 + fr;
                    ldm_x4(af[mt], abase + row * CH_STRIDE + s * 32 + fc);
                }
                #pragma unroll
                for (int bi = 0; bi < 2; bi++) {
                    int row = wn * 32 + bi * 16 + fr;
                    ldm_x4(bf[bi], bbase + row * CH_STRIDE + s * 32 + fc);
                }
                #pragma unroll
                for (int mt = 0; mt < 4; mt++)
                    #pragma unroll
                    for (int nt2 = 0; nt2 < 4; nt2++) {
                        int bi = nt2 >> 1, od = nt2 & 1;
                        MMA_F16(acc[mt][nt2],
                                af[mt][0], af[mt][1], af[mt][2], af[mt][3],
                                bf[bi][od], bf[bi][od + 2]);
                    }
            }
        }

        if (kt + 1 < 16) sts((kt + 1) & 1);
        __syncthreads();
    }

    #pragma unroll
    for (int mt = 0; mt < 4; mt++) {
        int m = m0 + wm * 64 + mt * 16 + r;
        #pragma unroll
        for (int nt = 0; nt < 4; nt++) {
            int n = n0g + wn * 32 + nt * 8 + c2;
            float* a = acc[mt][nt];
            float b0 = bias[n], b1 = bias[n + 1];
            *(float2*)(out + (size_t)m * 256 + n)       = make_float2(a[0] + b0, a[1] + b1);
            *(float2*)(out + (size_t)(m + 8) * 256 + n) = make_float2(a[2] + b0, a[3] + b1);
        }
    }
}

// ---------------------------------------------------------------------------
// Spatial linear attention (attend over N=2048). Block = (bt, h), 8 warps.
// fp16 in/out, f32 accumulation.
// ---------------------------------------------------------------------------
#define SQS 36
__global__ __launch_bounds__(256)
void spatial_attn_kernel(const __half* __restrict__ q, const __half* __restrict__ k,
                         const __half* __restrict__ v, __half* __restrict__ o)
{
    __shared__ float s_part[8][32][SQS];
    __shared__ float s_kvs[32][SQS];
    __shared__ float s_ksp[8][32];
    __shared__ float s_kss[32];

    const int bt = blockIdx.x;
    const int h  = blockIdx.y;
    const int tid = threadIdx.x;
    const int w = tid >> 5, lane = tid & 31;

    const size_t baseBT = (size_t)bt * N_ * D_ + h * HD_;

    const int mg = lane >> 2;
    const int dg = lane & 3;
    float acc[4][8] = {};
    float kss[4] = {0.f, 0.f, 0.f, 0.f};

    const int l0w = w * 256;
    #pragma unroll 4
    for (int l = l0w; l < l0w + 256; l++) {
        const __half* rk = k + baseBT + (size_t)l * D_;
        const __half* rv = v + baseBT + (size_t)l * D_;
        uint2 uk = *(const uint2*)(rk + mg * 4);
        uint4 uv = *(const uint4*)(rv + dg * 8);
        float2 k01 = h2f2(uk.x), k23 = h2f2(uk.y);
        float2 v01 = h2f2(uv.x), v23 = h2f2(uv.y);
        float2 v45 = h2f2(uv.z), v67 = h2f2(uv.w);
        float kk[4] = {k01.x, k01.y, k23.x, k23.y};
        float vv[8] = {v01.x, v01.y, v23.x, v23.y, v45.x, v45.y, v67.x, v67.y};
        #pragma unroll
        for (int i = 0; i < 4; i++) {
            kss[i] += kk[i];
            #pragma unroll
            for (int j = 0; j < 8; j++)
                acc[i][j] = fmaf(kk[i], vv[j], acc[i][j]);
        }
    }
    #pragma unroll
    for (int i = 0; i < 4; i++) {
        *(float4*)&s_part[w][mg*4+i][dg*8]     = make_float4(acc[i][0], acc[i][1], acc[i][2], acc[i][3]);
        *(float4*)&s_part[w][mg*4+i][dg*8 + 4] = make_float4(acc[i][4], acc[i][5], acc[i][6], acc[i][7]);
    }
    if (dg == 0) {
        #pragma unroll
        for (int i = 0; i < 4; i++) s_ksp[w][mg*4+i] = kss[i];
    }
    __syncthreads();

    {
        int m = tid >> 3, dd = (tid & 7) * 4;
        float4 s = make_float4(0.f, 0.f, 0.f, 0.f);
        #pragma unroll
        for (int wi = 0; wi < 8; wi++) {
            float4 p = *(const float4*)&s_part[wi][m][dd];
            s.x += p.x; s.y += p.y; s.z += p.z; s.w += p.w;
        }
        *(float4*)&s_kvs[m][dd] = s;
        if (tid < 32) {
            float s2 = 0.f;
            #pragma unroll
            for (int wi = 0; wi < 8; wi++) s2 += s_ksp[wi][tid];
            s_kss[tid] = s2;
        }
    }
    __syncthreads();

    float* qs = &s_part[w][0][0];
    const int lg = lane >> 3;
    const int d4 = (lane & 7) * 4;

    for (int c = 0; c < 8; c++) {
        const int l0 = l0w + c * 32;
        #pragma unroll
        for (int i2 = 0; i2 < 4; i2++) {
            int idx = lane + i2 * 32;          // 0..127
            int rr = idx >> 2, f = idx & 3;
            uint4 u = *(const uint4*)(q + baseBT + (size_t)(l0 + rr) * D_ + f * 8);
            float2 a = h2f2(u.x), b = h2f2(u.y), cc = h2f2(u.z), d = h2f2(u.w);
            *(float4*)(qs + rr * SQS + f * 8)     = make_float4(a.x, a.y, b.x, b.y);
            *(float4*)(qs + rr * SQS + f * 8 + 4) = make_float4(cc.x, cc.y, d.x, d.y);
        }
        __syncwarp();

        float num[8][4] = {};
        float den[8] = {};
        #pragma unroll
        for (int m = 0; m < 32; m++) {
            float km = s_kss[m];
            float4 kr = *(const float4*)&s_kvs[m][d4];
            #pragma unroll
            for (int i = 0; i < 8; i++) {
                float qm = qs[(i * 4 + lg) * SQS + m];
                den[i] = fmaf(qm, km, den[i]);
                num[i][0] = fmaf(qm, kr.x, num[i][0]);
                num[i][1] = fmaf(qm, kr.y, num[i][1]);
                num[i][2] = fmaf(qm, kr.z, num[i][2]);
                num[i][3] = fmaf(qm, kr.w, num[i][3]);
            }
        }
        #pragma unroll
        for (int i = 0; i < 8; i++) {
            int l = l0 + i * 4 + lg;
            uint2 uvv = *(const uint2*)(v + baseBT + (size_t)l * D_ + d4);
            float2 vx = h2f2(uvv.x), vy = h2f2(uvv.y);
            float ddn = fmaxf(den[i] + (float)N_, 1e-5f);
            float inv = 1.f / ddn;
            float r0 = (num[i][0] + (float)N_ * vx.x) * inv;
            float r1 = (num[i][1] + (float)N_ * vx.y) * inv;
            float r2 = (num[i][2] + (float)N_ * vy.x) * inv;
            float r3 = (num[i][3] + (float)N_ * vy.y) * inv;
            *(uint2*)(o + baseBT + (size_t)l * D_ + d4) =
                make_uint2(f2h2(r0, r1), f2h2(r2, r3));
        }
        __syncwarp();
    }
}

// ---------------------------------------------------------------------------
// Temporal linear attention (attend over T=24). Block = (b, n), warp = head.
// ---------------------------------------------------------------------------
#define TSM_KVS (8*32*SQS)
#define TSM_Q   (8*24*SQS)
#define TSM_BYTES ((TSM_KVS + TSM_Q + 8*32) * 4)
__global__ __launch_bounds__(256)
void temporal_attn_kernel(const __half* __restrict__ q, const __half* __restrict__ k,
                          const __half* __restrict__ v, __half* __restrict__ o)
{
    extern __shared__ float sm[];
    const int bn = blockIdx.x;
    const int b = bn >> 11;
    const int n = bn & 2047;
    const int tid = threadIdx.x;
    const int h = tid >> 5, lane = tid & 31;

    float* kvs_h = sm + h * 32 * SQS;
    float* q_h   = sm + TSM_KVS + h * 24 * SQS;
    float* kss_h = sm + TSM_KVS + TSM_Q + h * 32;

    const size_t base = ((size_t)b * T_ * N_ + n) * D_ + h * HD_;
    const size_t sT = (size_t)N_ * D_;

    const int mg = lane >> 2;
    const int dg = lane & 3;
    float acc[4][8] = {};
    float kss[4] = {0.f, 0.f, 0.f, 0.f};

    #pragma unroll
    for (int t = 0; t < T_; t++) {
        const __half* rk = k + base + (size_t)t * sT;
        const __half* rv = v + base + (size_t)t * sT;
        uint2 uk = *(const uint2*)(rk + mg * 4);
        uint4 uv = *(const uint4*)(rv + dg * 8);
        float2 k01 = h2f2(uk.x), k23 = h2f2(uk.y);
        float2 v01 = h2f2(uv.x), v23 = h2f2(uv.y);
        float2 v45 = h2f2(uv.z), v67 = h2f2(uv.w);
        float kk[4] = {k01.x, k01.y, k23.x, k23.y};
        float vv[8] = {v01.x, v01.y, v23.x, v23.y, v45.x, v45.y, v67.x, v67.y};
        #pragma unroll
        for (int i = 0; i < 4; i++) {
            kss[i] += kk[i];
            #pragma unroll
            for (int j = 0; j < 8; j++)
                acc[i][j] = fmaf(kk[i], vv[j], acc[i][j]);
        }
    }
    #pragma unroll
    for (int i = 0; i < 4; i++) {
        *(float4*)(kvs_h + (mg*4+i) * SQS + dg*8)     = make_float4(acc[i][0], acc[i][1], acc[i][2], acc[i][3]);
        *(float4*)(kvs_h + (mg*4+i) * SQS + dg*8 + 4) = make_float4(acc[i][4], acc[i][5], acc[i][6], acc[i][7]);
    }
    if (dg == 0) {
        #pragma unroll
        for (int i = 0; i < 4; i++) kss_h[mg*4+i] = kss[i];
    }
    #pragma unroll
    for (int i = 0; i < 3; i++) {
        int idx = lane + i * 32;               // 0..95
        int t = idx >> 2, f = idx & 3;
        uint4 u = *(const uint4*)(q + base + (size_t)t * sT + f * 8);
        float2 a = h2f2(u.x), bb = h2f2(u.y), cc = h2f2(u.z), d = h2f2(u.w);
        *(float4*)(q_h + t * SQS + f * 8)     = make_float4(a.x, a.y, bb.x, bb.y);
        *(float4*)(q_h + t * SQS + f * 8 + 4) = make_float4(cc.x, cc.y, d.x, d.y);
    }
    __syncwarp();

    const int tg = lane >> 3;
    const int d4 = (lane & 7) * 4;
    float num[6][4] = {};
    float den[6] = {};
    #pragma unroll
    for (int m = 0; m < 32; m++) {
        float km = kss_h[m];
        float4 kr = *(const float4*)(kvs_h + m * SQS + d4);
        #pragma unroll
        for (int i = 0; i < 6; i++) {
            float qm = q_h[(tg * 6 + i) * SQS + m];
            den[i] = fmaf(qm, km, den[i]);
            num[i][0] = fmaf(qm, kr.x, num[i][0]);
            num[i][1] = fmaf(qm, kr.y, num[i][1]);
            num[i][2] = fmaf(qm, kr.z, num[i][2]);
            num[i][3] = fmaf(qm, kr.w, num[i][3]);
        }
    }
    #pragma unroll
    for (int i = 0; i < 6; i++) {
        int t = tg * 6 + i;
        uint2 uvv = *(const uint2*)(v + base + (size_t)t * sT + d4);
        float2 vx = h2f2(uvv.x), vy = h2f2(uvv.y);
        float ddn = fmaxf(den[i] + (float)T_, 1e-5f);
        float inv = 1.f / ddn;
        float r0 = (num[i][0] + (float)T_ * vx.x) * inv;
        float r1 = (num[i][1] + (float)T_ * vx.y) * inv;
        float r2 = (num[i][2] + (float)T_ * vy.x) * inv;
        float r3 = (num[i][3] + (float)T_ * vy.y) * inv;
        *(uint2*)(o + base + (size_t)t * sT + d4) =
            make_uint2(f2h2(r0, r1), f2h2(r2, r3));
    }
}

// ---------------------------------------------------------------------------
extern "C" void kernel_launch(void* const* d_in, const int* in_sizes, int n_in,
                              void* d_out, int out_size)
{
    const float* x     = (const float*)d_in[0];
    const float* w_qkv = (const float*)d_in[1];
    const float* w_out = (const float*)d_in[2];
    const float* b_out = (const float*)d_in[3];
    float* out = (float*)d_out;

    __half *q, *k, *v, *os, *ot, *wqh, *woh;
    cudaGetSymbolAddress((void**)&q,   g_q);
    cudaGetSymbolAddress((void**)&k,   g_k);
    cudaGetSymbolAddress((void**)&v,   g_v);
    cudaGetSymbolAddress((void**)&os,  g_os);
    cudaGetSymbolAddress((void**)&ot,  g_ot);
    cudaGetSymbolAddress((void**)&wqh, g_wqh);
    cudaGetSymbolAddress((void**)&woh, g_woh);

    cudaFuncSetAttribute(gemm_qkv_kernel,
                         cudaFuncAttributeMaxDynamicSharedMemorySize, G1_SMEM);
    cudaFuncSetAttribute(gemm_out_kernel,
                         cudaFuncAttributeMaxDynamicSharedMemorySize, G2_SMEM);
    cudaFuncSetAttribute(temporal_attn_kernel,
                         cudaFuncAttributeMaxDynamicSharedMemorySize, TSM_BYTES);

    // 0) convert weights to fp16 scratch
    {
        int total = (768 * 256 + 256 * 512) / 2;
        cvt_weights_kernel<<<(total + 255) / 256, 256>>>(w_qkv, w_out, wqh, woh);
    }
    // 1) QKV projection (fp16 mma, A-resident) + fused q/k l2norm
    gemm_qkv_kernel<<<MTOK / 128, 256, G1_SMEM>>>(x, wqh, q, k, v);

    // 2) spatial attention
    {
        dim3 grid(B_ * T_, H_);
        spatial_attn_kernel<<<grid, 256>>>(q, k, v, os);
    }
    // 3) temporal attention
    temporal_attn_kernel<<<B_ * N_, 256, TSM_BYTES>>>(q, k, v, ot);

    // 4) output projection + bias (fp16 mma, dual-A concat)
    {
        dim3 grid(2, MTOK / 128);
        gemm_out_kernel<<<grid, 256, G2_SMEM>>>(os, ot, woh, b_out, out);
    }
}